// round 4
// baseline (speedup 1.0000x reference)
#include <cuda_runtime.h>
#include <math.h>

// Problem constants (fixed by the dataset)
#define NN    8000
#define BB    32
#define FF    66            // input_dim(2) + units(64)
#define NBF   (BB*FF)       // 2112
#define MM    5             // num diffusion matrices = 2*K+1
#define KDIM  (FF*MM)       // 330
#define UNITS 64
#define EMAX  64000

// ---------------- scratch (static device globals; no cudaMalloc allowed) ---------
__device__ float g_X0 [NN*NBF];                 // (N, B, F) current x0 (state gets overwritten in-place)
__device__ float g_X1a[NN*NBF];                 // S0 @ x0
__device__ float g_X1b[NN*NBF];                 // S1 @ x0
__device__ float g_A  [(size_t)NN*BB*KDIM];     // packed GEMM A: row=(n*B+b), col=f*5+m
__device__ float g_U  [(size_t)NN*BB*UNITS];    // update gate u
__device__ int   g_ptr0[NN+1], g_ptr1[NN+1];
__device__ int   g_cidx0[EMAX], g_cidx1[EMAX];
__device__ float g_cval0[EMAX], g_cval1[EMAX];
__device__ int   g_cnt[2*NN];
__device__ int   g_cur[2*NN];

// ---------------- CSR build --------------------------------------------------
__global__ void csr_prep() {
    int i = blockIdx.x * blockDim.x + threadIdx.x;
    if (i < 2*NN) { g_cnt[i] = 0; g_cur[i] = 0; }
}

__global__ void csr_count(const int* __restrict__ r0, const int* __restrict__ r1, int E) {
    int e = blockIdx.x * blockDim.x + threadIdx.x;
    if (e < E) {
        atomicAdd(&g_cnt[r0[e]], 1);
        atomicAdd(&g_cnt[NN + r1[e]], 1);
    }
}

// one block per support; exclusive scan of 8000 counts
__global__ void csr_scan() {
    int s = blockIdx.x;
    const int* cnt = g_cnt + s * NN;
    int* ptr = s ? g_ptr1 : g_ptr0;
    __shared__ int sm[1024];
    __shared__ int carry;
    if (threadIdx.x == 0) carry = 0;
    __syncthreads();
    for (int base = 0; base < NN; base += 1024) {
        int i = base + threadIdx.x;
        int v = (i < NN) ? cnt[i] : 0;
        sm[threadIdx.x] = v;
        __syncthreads();
        int c0 = carry;
        for (int off = 1; off < 1024; off <<= 1) {
            int t = (threadIdx.x >= (unsigned)off) ? sm[threadIdx.x - off] : 0;
            __syncthreads();
            sm[threadIdx.x] += t;
            __syncthreads();
        }
        if (i < NN) ptr[i] = c0 + sm[threadIdx.x] - v;
        __syncthreads();
        if (threadIdx.x == 1023) carry = c0 + sm[1023];
        __syncthreads();
    }
    if (threadIdx.x == 0) ptr[NN] = carry;
}

__global__ void csr_scatter(const int* __restrict__ r, const int* __restrict__ c,
                            const float* __restrict__ v, int E, int s) {
    int e = blockIdx.x * blockDim.x + threadIdx.x;
    if (e >= E) return;
    int row = r[e];
    int* cur = g_cur + s * NN;
    const int* ptr = s ? g_ptr1 : g_ptr0;
    int* ci = s ? g_cidx1 : g_cidx0;
    float* cv = s ? g_cval1 : g_cval0;
    int p = ptr[row] + atomicAdd(&cur[row], 1);
    ci[p] = c[e];
    cv[p] = v[e];
}

// ---------------- build x0 (N,B,F) from inputs (B,N,2) and hx (B,N,64) -------
__global__ void build_x0(const float* __restrict__ inputs, const float* __restrict__ hx) {
    int idx = blockIdx.x * blockDim.x + threadIdx.x;   // over NN*NBF
    int n = idx / NBF;
    int rem = idx - n * NBF;
    int b = rem / FF;
    int f = rem - b * FF;
    float v;
    if (f < 2) v = inputs[(size_t)b * (NN*2) + n*2 + f];
    else       v = hx[(size_t)b * (NN*UNITS) + n*UNITS + (f-2)];
    g_X0[idx] = v;
}

// ---------------- spmm: y = S @ x0, one block per node -----------------------
__global__ void spmm_kernel(int s) {
    const int*   ptr = s ? g_ptr1  : g_ptr0;
    const int*   ci  = s ? g_cidx1 : g_cidx0;
    const float* cv  = s ? g_cval1 : g_cval0;
    float*       y   = s ? g_X1b   : g_X1a;
    int n = blockIdx.x;
    int beg = ptr[n], end = ptr[n+1];
    for (int t = threadIdx.x; t < NBF; t += blockDim.x) {
        float acc = 0.f;
        for (int e = beg; e < end; e++)
            acc += cv[e] * g_X0[(size_t)ci[e] * NBF + t];
        y[(size_t)n * NBF + t] = acc;
    }
}

// ---------------- fused cheb-step-2 + pack into GEMM-A layout ----------------
// per node n: A[(n*B+b)][f*5 + m] for m in {x0, s0x1, s0x2, s1x1, s1x2}
// x2 = 2*S@x1 - x0 computed by gathering neighbors' x1
__global__ void chebpack_kernel() {
    int n = blockIdx.x;
    __shared__ float tile[BB * KDIM];   // 32*330*4 = 42240 B
    int b0 = g_ptr0[n], e0 = g_ptr0[n+1];
    int b1 = g_ptr1[n], e1 = g_ptr1[n+1];
    for (int t = threadIdx.x; t < NBF; t += blockDim.x) {
        int b = t / FF, f = t - b * FF;
        float v0 = g_X0[(size_t)n * NBF + t];
        float a2 = -v0, a4 = -v0;
        for (int e = b0; e < e0; e++)
            a2 += 2.f * g_cval0[e] * g_X1a[(size_t)g_cidx0[e] * NBF + t];
        for (int e = b1; e < e1; e++)
            a4 += 2.f * g_cval1[e] * g_X1b[(size_t)g_cidx1[e] * NBF + t];
        int base = b * KDIM + f * MM;
        tile[base + 0] = v0;
        tile[base + 1] = g_X1a[(size_t)n * NBF + t];
        tile[base + 2] = a2;
        tile[base + 3] = g_X1b[(size_t)n * NBF + t];
        tile[base + 4] = a4;
    }
    __syncthreads();
    float* Arow = g_A + (size_t)n * (BB * KDIM);
    for (int i = threadIdx.x; i < BB * KDIM; i += blockDim.x)
        Arow[i] = tile[i];
}

// ---------------- GEMM1: (256000 x 330) @ (330 x 128), sigmoid, r/u split ----
// epilogue: r -> X0 state part (r*hx), u -> g_U
__global__ void gemm1_kernel(const float* __restrict__ W, const float* __restrict__ bias,
                             const float* __restrict__ hx) {
    __shared__ float As[16][132];
    __shared__ float Ws[16][128];
    int tx = threadIdx.x & 15, ty = threadIdx.x >> 4;   // 16x16
    int rowBase = blockIdx.x * 128;
    float acc[8][8];
    #pragma unroll
    for (int i = 0; i < 8; i++)
        #pragma unroll
        for (int j = 0; j < 8; j++) acc[i][j] = 0.f;

    for (int kt = 0; kt < 21; kt++) {
        int k0 = kt * 16;
        #pragma unroll
        for (int i = 0; i < 8; i++) {
            int lin = threadIdx.x + i * 256;       // 0..2047
            int r = lin >> 4, kk = lin & 15;
            int k = k0 + kk;
            As[kk][r] = (k < KDIM) ? g_A[(size_t)(rowBase + r) * KDIM + k] : 0.f;
        }
        #pragma unroll
        for (int i = 0; i < 8; i++) {
            int lin = threadIdx.x + i * 256;
            int kk = lin >> 7, c = lin & 127;
            int k = k0 + kk;
            Ws[kk][c] = (k < KDIM) ? W[k * 128 + c] : 0.f;
        }
        __syncthreads();
        #pragma unroll
        for (int k = 0; k < 16; k++) {
            float a[8], w[8];
            #pragma unroll
            for (int i = 0; i < 8; i++) a[i] = As[k][ty*8 + i];
            #pragma unroll
            for (int j = 0; j < 8; j++) w[j] = Ws[k][tx*8 + j];
            #pragma unroll
            for (int i = 0; i < 8; i++)
                #pragma unroll
                for (int j = 0; j < 8; j++) acc[i][j] += a[i] * w[j];
        }
        __syncthreads();
    }
    #pragma unroll
    for (int i = 0; i < 8; i++) {
        int row = rowBase + ty*8 + i;
        int n = row >> 5, b = row & 31;
        #pragma unroll
        for (int j = 0; j < 8; j++) {
            int col = tx*8 + j;
            float v = acc[i][j] + bias[col];
            v = 1.f / (1.f + __expf(-v));
            if (col < UNITS) {
                float h = hx[(size_t)b * (NN*UNITS) + n*UNITS + col];
                g_X0[(size_t)n * NBF + b*FF + 2 + col] = v * h;   // state = r*hx
            } else {
                g_U[(size_t)row * UNITS + (col - UNITS)] = v;
            }
        }
    }
}

// ---------------- GEMM2: (256000 x 330) @ (330 x 64), tanh, final combine ----
__global__ void gemm2_kernel(const float* __restrict__ W, const float* __restrict__ bias,
                             const float* __restrict__ hx, float* __restrict__ out) {
    __shared__ float As[16][132];
    __shared__ float Ws[16][64];
    int tx = threadIdx.x & 15, ty = threadIdx.x >> 4;   // cols: tx*4, rows: ty*8
    int rowBase = blockIdx.x * 128;
    float acc[8][4];
    #pragma unroll
    for (int i = 0; i < 8; i++)
        #pragma unroll
        for (int j = 0; j < 4; j++) acc[i][j] = 0.f;

    for (int kt = 0; kt < 21; kt++) {
        int k0 = kt * 16;
        #pragma unroll
        for (int i = 0; i < 8; i++) {
            int lin = threadIdx.x + i * 256;
            int r = lin >> 4, kk = lin & 15;
            int k = k0 + kk;
            As[kk][r] = (k < KDIM) ? g_A[(size_t)(rowBase + r) * KDIM + k] : 0.f;
        }
        #pragma unroll
        for (int i = 0; i < 4; i++) {
            int lin = threadIdx.x + i * 256;       // 0..1023
            int kk = lin >> 6, c = lin & 63;
            int k = k0 + kk;
            Ws[kk][c] = (k < KDIM) ? W[k * 64 + c] : 0.f;
        }
        __syncthreads();
        #pragma unroll
        for (int k = 0; k < 16; k++) {
            float a[8], w[4];
            #pragma unroll
            for (int i = 0; i < 8; i++) a[i] = As[k][ty*8 + i];
            #pragma unroll
            for (int j = 0; j < 4; j++) w[j] = Ws[k][tx*4 + j];
            #pragma unroll
            for (int i = 0; i < 8; i++)
                #pragma unroll
                for (int j = 0; j < 4; j++) acc[i][j] += a[i] * w[j];
        }
        __syncthreads();
    }
    #pragma unroll
    for (int i = 0; i < 8; i++) {
        int row = rowBase + ty*8 + i;
        int n = row >> 5, b = row & 31;
        #pragma unroll
        for (int j = 0; j < 4; j++) {
            int col = tx*4 + j;
            float c = tanhf(acc[i][j] + bias[col]);
            float u = g_U[(size_t)row * UNITS + col];
            float h = hx[(size_t)b * (NN*UNITS) + n*UNITS + col];
            out[(size_t)b * (NN*UNITS) + n*UNITS + col] = u * h + (1.f - u) * c;
        }
    }
}

// ---------------- launch -----------------------------------------------------
extern "C" void kernel_launch(void* const* d_in, const int* in_sizes, int n_in,
                              void* d_out, int out_size) {
    const float* inputs = (const float*)d_in[0];
    const float* hx     = (const float*)d_in[1];
    const float* W_ru   = (const float*)d_in[2];
    const float* b_ru   = (const float*)d_in[3];
    const float* W_c    = (const float*)d_in[4];
    const float* b_c    = (const float*)d_in[5];
    const int*   s0r    = (const int*)d_in[6];
    const int*   s0c    = (const int*)d_in[7];
    const float* s0v    = (const float*)d_in[8];
    const int*   s1r    = (const int*)d_in[9];
    const int*   s1c    = (const int*)d_in[10];
    const float* s1v    = (const float*)d_in[11];
    int E = in_sizes[6];
    float* out = (float*)d_out;

    // CSR build (both supports), done every call (deterministic work graph)
    csr_prep<<<(2*NN + 255)/256, 256>>>();
    csr_count<<<(E + 255)/256, 256>>>(s0r, s1r, E);
    csr_scan<<<2, 1024>>>();
    csr_scatter<<<(E + 255)/256, 256>>>(s0r, s0c, s0v, E, 0);
    csr_scatter<<<(E + 255)/256, 256>>>(s1r, s1c, s1v, E, 1);

    // gconv #1 (gates)
    build_x0<<<(NN*NBF)/256, 256>>>(inputs, hx);
    spmm_kernel<<<NN, 256>>>(0);
    spmm_kernel<<<NN, 256>>>(1);
    chebpack_kernel<<<NN, 256>>>();
    gemm1_kernel<<<(NN*BB)/128, 256>>>(W_ru, b_ru, hx);   // also writes state = r*hx into g_X0

    // gconv #2 (candidate) + final combine
    spmm_kernel<<<NN, 256>>>(0);
    spmm_kernel<<<NN, 256>>>(1);
    chebpack_kernel<<<NN, 256>>>();
    gemm2_kernel<<<(NN*BB)/128, 256>>>(W_c, b_c, hx, out);
}

// round 7
// speedup vs baseline: 1.1702x; 1.1702x over previous
#include <cuda_runtime.h>
#include <math.h>

// Problem constants (fixed by the dataset)
#define NN    8000
#define BB    32
#define FF    66            // input_dim(2) + units(64)
#define NBF   (BB*FF)       // 2112
#define MM    5             // num diffusion matrices = 2*K+1
#define KDIM  (FF*MM)       // 330
#define UNITS 64
#define EMAX  64000

// ---------------- scratch (static device globals; no cudaMalloc allowed) ---------
__device__ float g_X0 [NN*NBF];                 // (N, B, F) current x0 (state gets overwritten in-place)
__device__ float g_X1a[NN*NBF];                 // S0 @ x0
__device__ float g_X1b[NN*NBF];                 // S1 @ x0
__device__ float g_A  [(size_t)NN*BB*KDIM];     // packed GEMM A: row=(n*B+b), col=f*5+m
__device__ float g_U  [(size_t)NN*BB*UNITS];    // update gate u
__device__ int   g_ptr0[NN+1], g_ptr1[NN+1];
__device__ int   g_cidx0[EMAX], g_cidx1[EMAX];
__device__ float g_cval0[EMAX], g_cval1[EMAX];
__device__ int   g_cnt[2*NN];
__device__ int   g_cur[2*NN];

// ---------------- CSR build --------------------------------------------------
__global__ void csr_prep() {
    int i = blockIdx.x * blockDim.x + threadIdx.x;
    if (i < 2*NN) { g_cnt[i] = 0; g_cur[i] = 0; }
}

__global__ void csr_count(const int* __restrict__ r0, const int* __restrict__ r1, int E) {
    int e = blockIdx.x * blockDim.x + threadIdx.x;
    if (e < E) {
        atomicAdd(&g_cnt[r0[e]], 1);
        atomicAdd(&g_cnt[NN + r1[e]], 1);
    }
}

// one block per support; exclusive scan of 8000 counts
__global__ void csr_scan() {
    int s = blockIdx.x;
    const int* cnt = g_cnt + s * NN;
    int* ptr = s ? g_ptr1 : g_ptr0;
    __shared__ int sm[1024];
    __shared__ int carry;
    if (threadIdx.x == 0) carry = 0;
    __syncthreads();
    for (int base = 0; base < NN; base += 1024) {
        int i = base + threadIdx.x;
        int v = (i < NN) ? cnt[i] : 0;
        sm[threadIdx.x] = v;
        __syncthreads();
        int c0 = carry;
        for (int off = 1; off < 1024; off <<= 1) {
            int t = (threadIdx.x >= (unsigned)off) ? sm[threadIdx.x - off] : 0;
            __syncthreads();
            sm[threadIdx.x] += t;
            __syncthreads();
        }
        if (i < NN) ptr[i] = c0 + sm[threadIdx.x] - v;
        __syncthreads();
        if (threadIdx.x == 1023) carry = c0 + sm[1023];
        __syncthreads();
    }
    if (threadIdx.x == 0) ptr[NN] = carry;
}

__global__ void csr_scatter(const int* __restrict__ r, const int* __restrict__ c,
                            const float* __restrict__ v, int E, int s) {
    int e = blockIdx.x * blockDim.x + threadIdx.x;
    if (e >= E) return;
    int row = r[e];
    int* cur = g_cur + s * NN;
    const int* ptr = s ? g_ptr1 : g_ptr0;
    int* ci = s ? g_cidx1 : g_cidx0;
    float* cv = s ? g_cval1 : g_cval0;
    int p = ptr[row] + atomicAdd(&cur[row], 1);
    ci[p] = c[e];
    cv[p] = v[e];
}

// ---------------- build x0 (N,B,F) from inputs (B,N,2) and hx (B,N,64) -------
__global__ void build_x0(const float* __restrict__ inputs, const float* __restrict__ hx) {
    int idx = blockIdx.x * blockDim.x + threadIdx.x;   // over NN*NBF
    int n = idx / NBF;
    int rem = idx - n * NBF;
    int b = rem / FF;
    int f = rem - b * FF;
    float v;
    if (f < 2) v = inputs[(size_t)b * (NN*2) + n*2 + f];
    else       v = hx[(size_t)b * (NN*UNITS) + n*UNITS + (f-2)];
    g_X0[idx] = v;
}

// ---------------- spmm: y = S @ x0, one block per node -----------------------
__global__ void spmm_kernel(int s) {
    const int*   ptr = s ? g_ptr1  : g_ptr0;
    const int*   ci  = s ? g_cidx1 : g_cidx0;
    const float* cv  = s ? g_cval1 : g_cval0;
    float*       y   = s ? g_X1b   : g_X1a;
    int n = blockIdx.x;
    int beg = ptr[n], end = ptr[n+1];
    for (int t = threadIdx.x; t < NBF; t += blockDim.x) {
        float acc = 0.f;
        for (int e = beg; e < end; e++)
            acc += cv[e] * g_X0[(size_t)ci[e] * NBF + t];
        y[(size_t)n * NBF + t] = acc;
    }
}

// ---------------- fused cheb-step-2 + pack into GEMM-A layout ----------------
__global__ void chebpack_kernel() {
    int n = blockIdx.x;
    __shared__ float tile[BB * KDIM];   // 32*330*4 = 42240 B
    int b0 = g_ptr0[n], e0 = g_ptr0[n+1];
    int b1 = g_ptr1[n], e1 = g_ptr1[n+1];
    for (int t = threadIdx.x; t < NBF; t += blockDim.x) {
        int b = t / FF, f = t - b * FF;
        float v0 = g_X0[(size_t)n * NBF + t];
        float a2 = -v0, a4 = -v0;
        for (int e = b0; e < e0; e++)
            a2 += 2.f * g_cval0[e] * g_X1a[(size_t)g_cidx0[e] * NBF + t];
        for (int e = b1; e < e1; e++)
            a4 += 2.f * g_cval1[e] * g_X1b[(size_t)g_cidx1[e] * NBF + t];
        int base = b * KDIM + f * MM;
        tile[base + 0] = v0;
        tile[base + 1] = g_X1a[(size_t)n * NBF + t];
        tile[base + 2] = a2;
        tile[base + 3] = g_X1b[(size_t)n * NBF + t];
        tile[base + 4] = a4;
    }
    __syncthreads();
    float* Arow = g_A + (size_t)n * (BB * KDIM);
    for (int i = threadIdx.x; i < BB * KDIM; i += blockDim.x)
        Arow[i] = tile[i];
}

// ---------------- tensor-core helpers ----------------------------------------
__device__ __forceinline__ unsigned f2tf32(float x) {
    unsigned r;
    asm("cvt.rna.tf32.f32 %0, %1;" : "=r"(r) : "f"(x));
    return r;
}

__device__ __forceinline__ void mma_tf32(float* d, const unsigned* a, const unsigned* b) {
    asm volatile(
        "mma.sync.aligned.m16n8k8.row.col.f32.tf32.tf32.f32 "
        "{%0,%1,%2,%3}, {%4,%5,%6,%7}, {%8,%9}, {%0,%1,%2,%3};\n"
        : "+f"(d[0]), "+f"(d[1]), "+f"(d[2]), "+f"(d[3])
        : "r"(a[0]), "r"(a[1]), "r"(a[2]), "r"(a[3]), "r"(b[0]), "r"(b[1]));
}

#define NCHUNK 11   // ceil(330/32)

// ---------------- GEMM1 (tf32 mma): (256000 x 330) @ (330 x 128) --------------
// epilogue: sigmoid; r -> g_X0 state part (r*hx), u -> g_U
__global__ __launch_bounds__(256) void gemm1_kernel(
        const float* __restrict__ W, const float* __restrict__ bias,
        const float* __restrict__ hx) {
    __shared__ unsigned As[128][36];   // [row][k], pad 36 -> conflict-free frags
    __shared__ unsigned Ws[32][136];   // [k][col], pad 136

    int tid = threadIdx.x;
    int lane = tid & 31, w = tid >> 5;
    int warpM = w >> 1, warpN = w & 1;          // 4 x 2 warps: warp tile 32 x 64
    int g = lane >> 2, t = lane & 3;
    int rowBase = blockIdx.x * 128;

    float acc[2][8][4];
    #pragma unroll
    for (int i = 0; i < 2; i++)
        #pragma unroll
        for (int j = 0; j < 8; j++)
            #pragma unroll
            for (int q = 0; q < 4; q++) acc[i][j][q] = 0.f;

    for (int kt = 0; kt < NCHUNK; kt++) {
        int k0 = kt * 32;
        // stage A tile (128 x 32) as tf32
        #pragma unroll
        for (int i = 0; i < 16; i++) {
            int idx = tid + i * 256;            // 0..4095
            int r = idx >> 5, kk = idx & 31;
            int k = k0 + kk;
            float v = (k < KDIM) ? g_A[(size_t)(rowBase + r) * KDIM + k] : 0.f;
            As[r][kk] = f2tf32(v);
        }
        // stage W tile (32 x 128) as tf32
        #pragma unroll
        for (int i = 0; i < 16; i++) {
            int idx = tid + i * 256;
            int kk = idx >> 7, c = idx & 127;
            int k = k0 + kk;
            float v = (k < KDIM) ? W[k * 128 + c] : 0.f;
            Ws[kk][c] = f2tf32(v);
        }
        __syncthreads();
        #pragma unroll
        for (int ks = 0; ks < 4; ks++) {
            int k = ks * 8;
            unsigned a[2][4], b[8][2];
            #pragma unroll
            for (int i = 0; i < 2; i++) {
                int r = warpM * 32 + i * 16 + g;
                a[i][0] = As[r][k + t];
                a[i][1] = As[r + 8][k + t];
                a[i][2] = As[r][k + t + 4];
                a[i][3] = As[r + 8][k + t + 4];
            }
            #pragma unroll
            for (int j = 0; j < 8; j++) {
                int c = warpN * 64 + j * 8 + g;
                b[j][0] = Ws[k + t][c];
                b[j][1] = Ws[k + t + 4][c];
            }
            #pragma unroll
            for (int i = 0; i < 2; i++)
                #pragma unroll
                for (int j = 0; j < 8; j++)
                    mma_tf32(acc[i][j], a[i], b[j]);
        }
        __syncthreads();
    }

    // epilogue
    #pragma unroll
    for (int i = 0; i < 2; i++) {
        #pragma unroll
        for (int j = 0; j < 8; j++) {
            int col0 = warpN * 64 + j * 8 + 2 * t;
            #pragma unroll
            for (int half = 0; half < 2; half++) {    // c0,c1 (row g) / c2,c3 (row g+8)
                int row = rowBase + warpM * 32 + i * 16 + g + half * 8;
                int n = row >> 5, bb = row & 31;
                #pragma unroll
                for (int q = 0; q < 2; q++) {
                    int col = col0 + q;
                    float v = acc[i][j][half * 2 + q] + bias[col];
                    v = 1.f / (1.f + __expf(-v));
                    if (col < UNITS) {
                        float h = hx[(size_t)bb * (NN*UNITS) + n*UNITS + col];
                        g_X0[(size_t)n * NBF + bb*FF + 2 + col] = v * h;   // state = r*hx
                    } else {
                        g_U[(size_t)row * UNITS + (col - UNITS)] = v;
                    }
                }
            }
        }
    }
}

// ---------------- GEMM2 (tf32 mma): (256000 x 330) @ (330 x 64) ---------------
// epilogue: tanh; out = u*hx + (1-u)*c
__global__ __launch_bounds__(256) void gemm2_kernel(
        const float* __restrict__ W, const float* __restrict__ bias,
        const float* __restrict__ hx, float* __restrict__ out) {
    __shared__ unsigned As[128][36];
    __shared__ unsigned Ws[32][72];    // [k][col], pad 72 -> conflict-free

    int tid = threadIdx.x;
    int lane = tid & 31, w = tid >> 5;
    int warpM = w >> 1, warpN = w & 1;          // 4 x 2 warps: warp tile 32 x 32
    int g = lane >> 2, t = lane & 3;
    int rowBase = blockIdx.x * 128;

    float acc[2][4][4];
    #pragma unroll
    for (int i = 0; i < 2; i++)
        #pragma unroll
        for (int j = 0; j < 4; j++)
            #pragma unroll
            for (int q = 0; q < 4; q++) acc[i][j][q] = 0.f;

    for (int kt = 0; kt < NCHUNK; kt++) {
        int k0 = kt * 32;
        #pragma unroll
        for (int i = 0; i < 16; i++) {
            int idx = tid + i * 256;
            int r = idx >> 5, kk = idx & 31;
            int k = k0 + kk;
            float v = (k < KDIM) ? g_A[(size_t)(rowBase + r) * KDIM + k] : 0.f;
            As[r][kk] = f2tf32(v);
        }
        #pragma unroll
        for (int i = 0; i < 8; i++) {
            int idx = tid + i * 256;            // 0..2047
            int kk = idx >> 6, c = idx & 63;
            int k = k0 + kk;
            float v = (k < KDIM) ? W[k * 64 + c] : 0.f;
            Ws[kk][c] = f2tf32(v);
        }
        __syncthreads();
        #pragma unroll
        for (int ks = 0; ks < 4; ks++) {
            int k = ks * 8;
            unsigned a[2][4], b[4][2];
            #pragma unroll
            for (int i = 0; i < 2; i++) {
                int r = warpM * 32 + i * 16 + g;
                a[i][0] = As[r][k + t];
                a[i][1] = As[r + 8][k + t];
                a[i][2] = As[r][k + t + 4];
                a[i][3] = As[r + 8][k + t + 4];
            }
            #pragma unroll
            for (int j = 0; j < 4; j++) {
                int c = warpN * 32 + j * 8 + g;
                b[j][0] = Ws[k + t][c];
                b[j][1] = Ws[k + t + 4][c];
            }
            #pragma unroll
            for (int i = 0; i < 2; i++)
                #pragma unroll
                for (int j = 0; j < 4; j++)
                    mma_tf32(acc[i][j], a[i], b[j]);
        }
        __syncthreads();
    }

    #pragma unroll
    for (int i = 0; i < 2; i++) {
        #pragma unroll
        for (int j = 0; j < 4; j++) {
            int col0 = warpN * 32 + j * 8 + 2 * t;
            #pragma unroll
            for (int half = 0; half < 2; half++) {
                int row = rowBase + warpM * 32 + i * 16 + g + half * 8;
                int n = row >> 5, bb = row & 31;
                #pragma unroll
                for (int q = 0; q < 2; q++) {
                    int col = col0 + q;
                    float c = tanhf(acc[i][j][half * 2 + q] + bias[col]);
                    float u = g_U[(size_t)row * UNITS + col];
                    float h = hx[(size_t)bb * (NN*UNITS) + n*UNITS + col];
                    out[(size_t)bb * (NN*UNITS) + n*UNITS + col] = u * h + (1.f - u) * c;
                }
            }
        }
    }
}

// ---------------- launch -----------------------------------------------------
extern "C" void kernel_launch(void* const* d_in, const int* in_sizes, int n_in,
                              void* d_out, int out_size) {
    const float* inputs = (const float*)d_in[0];
    const float* hx     = (const float*)d_in[1];
    const float* W_ru   = (const float*)d_in[2];
    const float* b_ru   = (const float*)d_in[3];
    const float* W_c    = (const float*)d_in[4];
    const float* b_c    = (const float*)d_in[5];
    const int*   s0r    = (const int*)d_in[6];
    const int*   s0c    = (const int*)d_in[7];
    const float* s0v    = (const float*)d_in[8];
    const int*   s1r    = (const int*)d_in[9];
    const int*   s1c    = (const int*)d_in[10];
    const float* s1v    = (const float*)d_in[11];
    int E = in_sizes[6];
    float* out = (float*)d_out;

    // CSR build (both supports)
    csr_prep<<<(2*NN + 255)/256, 256>>>();
    csr_count<<<(E + 255)/256, 256>>>(s0r, s1r, E);
    csr_scan<<<2, 1024>>>();
    csr_scatter<<<(E + 255)/256, 256>>>(s0r, s0c, s0v, E, 0);
    csr_scatter<<<(E + 255)/256, 256>>>(s1r, s1c, s1v, E, 1);

    // gconv #1 (gates)
    build_x0<<<(NN*NBF)/256, 256>>>(inputs, hx);
    spmm_kernel<<<NN, 256>>>(0);
    spmm_kernel<<<NN, 256>>>(1);
    chebpack_kernel<<<NN, 256>>>();
    gemm1_kernel<<<(NN*BB)/128, 256>>>(W_ru, b_ru, hx);   // writes state = r*hx into g_X0

    // gconv #2 (candidate) + final combine
    spmm_kernel<<<NN, 256>>>(0);
    spmm_kernel<<<NN, 256>>>(1);
    chebpack_kernel<<<NN, 256>>>();
    gemm2_kernel<<<(NN*BB)/128, 256>>>(W_c, b_c, hx, out);
}

// round 9
// speedup vs baseline: 1.8441x; 1.5759x over previous
#include <cuda_runtime.h>
#include <cuda_fp16.h>
#include <math.h>

// Problem constants (fixed by the dataset)
#define NN    8000
#define BB    32
#define FF    66            // input_dim(2) + units(64)
#define NBF   (BB*FF)       // 2112
#define MM    5             // num diffusion matrices = 2*K+1
#define KDIM  (FF*MM)       // 330
#define UNITS 64
#define EMAX  64000
#define VEC   (NBF/8)       // 264 uint4 (8 halves) per node row

// ---------------- scratch (static device globals; no cudaMalloc allowed) ------
__device__ __align__(16) __half g_X0h [NN*NBF];             // (N, B, F) fp16
__device__ __align__(16) __half g_X1ah[NN*NBF];             // S0 @ x0
__device__ __align__(16) __half g_X1bh[NN*NBF];             // S1 @ x0
__device__ __align__(16) __half g_Ah  [(size_t)NN*BB*KDIM]; // packed GEMM A (fp16)
__device__ float g_U  [(size_t)NN*BB*UNITS];                // update gate u (fp32)
__device__ int   g_ptr0[NN+1], g_ptr1[NN+1];
__device__ int   g_cidx0[EMAX], g_cidx1[EMAX];
__device__ float g_cval0[EMAX], g_cval1[EMAX];
__device__ int   g_cnt[2*NN];
__device__ int   g_cur[2*NN];

// ---------------- CSR build ---------------------------------------------------
__global__ void csr_prep() {
    int i = blockIdx.x * blockDim.x + threadIdx.x;
    if (i < 2*NN) { g_cnt[i] = 0; g_cur[i] = 0; }
}

__global__ void csr_count(const int* __restrict__ r0, const int* __restrict__ r1, int E) {
    int e = blockIdx.x * blockDim.x + threadIdx.x;
    if (e < E) {
        atomicAdd(&g_cnt[r0[e]], 1);
        atomicAdd(&g_cnt[NN + r1[e]], 1);
    }
}

__global__ void csr_scan() {
    int s = blockIdx.x;
    const int* cnt = g_cnt + s * NN;
    int* ptr = s ? g_ptr1 : g_ptr0;
    __shared__ int sm[1024];
    __shared__ int carry;
    if (threadIdx.x == 0) carry = 0;
    __syncthreads();
    for (int base = 0; base < NN; base += 1024) {
        int i = base + threadIdx.x;
        int v = (i < NN) ? cnt[i] : 0;
        sm[threadIdx.x] = v;
        __syncthreads();
        int c0 = carry;
        for (int off = 1; off < 1024; off <<= 1) {
            int t = (threadIdx.x >= (unsigned)off) ? sm[threadIdx.x - off] : 0;
            __syncthreads();
            sm[threadIdx.x] += t;
            __syncthreads();
        }
        if (i < NN) ptr[i] = c0 + sm[threadIdx.x] - v;
        __syncthreads();
        if (threadIdx.x == 1023) carry = c0 + sm[1023];
        __syncthreads();
    }
    if (threadIdx.x == 0) ptr[NN] = carry;
}

__global__ void csr_scatter(const int* __restrict__ r, const int* __restrict__ c,
                            const float* __restrict__ v, int E, int s) {
    int e = blockIdx.x * blockDim.x + threadIdx.x;
    if (e >= E) return;
    int row = r[e];
    int* cur = g_cur + s * NN;
    const int* ptr = s ? g_ptr1 : g_ptr0;
    int* ci = s ? g_cidx1 : g_cidx0;
    float* cv = s ? g_cval1 : g_cval0;
    int p = ptr[row] + atomicAdd(&cur[row], 1);
    ci[p] = c[e];
    cv[p] = v[e];
}

// ---------------- build x0 (N,B,F) fp16 from inputs (B,N,2) + hx (B,N,64) ----
__global__ void build_x0(const float* __restrict__ inputs, const float* __restrict__ hx) {
    int idx = blockIdx.x * blockDim.x + threadIdx.x;   // over NN*NBF
    int n = idx / NBF;
    int rem = idx - n * NBF;
    int b = rem / FF;
    int f = rem - b * FF;
    float v;
    if (f < 2) v = inputs[(size_t)b * (NN*2) + n*2 + f];
    else       v = hx[(size_t)b * (NN*UNITS) + n*UNITS + (f-2)];
    g_X0h[idx] = __float2half_rn(v);
}

// ---------------- fma helper: acc[8] += w * unpack(uint4 of 8 halves) --------
__device__ __forceinline__ void hfma8(float* acc, uint4 v, float w) {
    const __half2* h = (const __half2*)&v;
    #pragma unroll
    for (int p = 0; p < 4; p++) {
        float2 f = __half22float2(h[p]);
        acc[2*p]   += w * f.x;
        acc[2*p+1] += w * f.y;
    }
}

// ---------------- spmm: y = S @ x0 (both supports), one block per (node, s) --
__global__ void spmm_h() {
    int s = blockIdx.y;
    const int*   ptr = s ? g_ptr1  : g_ptr0;
    const int*   ci  = s ? g_cidx1 : g_cidx0;
    const float* cv  = s ? g_cval1 : g_cval0;
    __half*      y   = s ? g_X1bh  : g_X1ah;
    const uint4* X   = (const uint4*)g_X0h;
    int n = blockIdx.x;
    int beg = ptr[n], end = ptr[n+1];
    for (int i = threadIdx.x; i < VEC; i += blockDim.x) {
        float acc[8];
        #pragma unroll
        for (int j = 0; j < 8; j++) acc[j] = 0.f;
        for (int e = beg; e < end; e++) {
            uint4 v = X[(size_t)ci[e] * VEC + i];
            hfma8(acc, v, cv[e]);
        }
        uint4 o;
        __half2* oh = (__half2*)&o;
        #pragma unroll
        for (int p = 0; p < 4; p++)
            oh[p] = __floats2half2_rn(acc[2*p], acc[2*p+1]);
        ((uint4*)y)[(size_t)n * VEC + i] = o;
    }
}

// ---------------- fused cheb-step-2 + pack into GEMM-A (fp16) -----------------
__global__ void chebpack_h() {
    int n = blockIdx.x;
    __shared__ __align__(16) __half tile[BB * KDIM];   // 10560 halves = 21120 B
    int b0 = g_ptr0[n], e0 = g_ptr0[n+1];
    int b1 = g_ptr1[n], e1 = g_ptr1[n+1];
    const uint4* X0 = (const uint4*)g_X0h;
    const uint4* XA = (const uint4*)g_X1ah;
    const uint4* XB = (const uint4*)g_X1bh;

    for (int i = threadIdx.x; i < VEC; i += blockDim.x) {
        uint4 v0 = X0[(size_t)n * VEC + i];
        uint4 va = XA[(size_t)n * VEC + i];
        uint4 vb = XB[(size_t)n * VEC + i];
        float a2[8], a4[8];
        {
            const __half2* h = (const __half2*)&v0;
            #pragma unroll
            for (int p = 0; p < 4; p++) {
                float2 f = __half22float2(h[p]);
                a2[2*p] = -f.x; a2[2*p+1] = -f.y;
                a4[2*p] = -f.x; a4[2*p+1] = -f.y;
            }
        }
        for (int e = b0; e < e0; e++)
            hfma8(a2, XA[(size_t)g_cidx0[e] * VEC + i], 2.f * g_cval0[e]);
        for (int e = b1; e < e1; e++)
            hfma8(a4, XB[(size_t)g_cidx1[e] * VEC + i], 2.f * g_cval1[e]);

        const __half* h0 = (const __half*)&v0;
        const __half* ha = (const __half*)&va;
        const __half* hb = (const __half*)&vb;
        #pragma unroll
        for (int j = 0; j < 8; j++) {
            int h = i * 8 + j;
            int b = h / FF, f = h - b * FF;
            int base = b * KDIM + f * MM;
            tile[base + 0] = h0[j];
            tile[base + 1] = ha[j];
            tile[base + 2] = __float2half_rn(a2[j]);
            tile[base + 3] = hb[j];
            tile[base + 4] = __float2half_rn(a4[j]);
        }
    }
    __syncthreads();
    // copy out coalesced: 32*330 halves = 660 uint4
    const uint4* src = (const uint4*)tile;
    uint4* dst = (uint4*)(g_Ah + (size_t)n * (BB * KDIM));
    for (int i = threadIdx.x; i < (BB * KDIM) / 8; i += blockDim.x)
        dst[i] = src[i];
}

// ---------------- fp16 mma helper ---------------------------------------------
__device__ __forceinline__ void mma_f16(float* d, const unsigned* a, const unsigned* b) {
    asm volatile(
        "mma.sync.aligned.m16n8k16.row.col.f32.f16.f16.f32 "
        "{%0,%1,%2,%3}, {%4,%5,%6,%7}, {%8,%9}, {%0,%1,%2,%3};\n"
        : "+f"(d[0]), "+f"(d[1]), "+f"(d[2]), "+f"(d[3])
        : "r"(a[0]), "r"(a[1]), "r"(a[2]), "r"(a[3]), "r"(b[0]), "r"(b[1]));
}

#define NCHUNK 11   // ceil(330/32)
#define ASTR   40   // smem stride in halves (conflict-free: 20 banks apart per row)

// ---------------- GEMM1 (fp16 mma): (256000 x 330) @ (330 x 128) --------------
// epilogue: sigmoid; r -> g_X0h state part (r*hx), u -> g_U
__global__ __launch_bounds__(256) void gemm1_kernel(
        const float* __restrict__ W, const float* __restrict__ bias,
        const float* __restrict__ hx) {
    __shared__ __half As [128][ASTR];   // [row][k]
    __shared__ __half Wst[128][ASTR];   // [col][k] (transposed on stage)

    int tid = threadIdx.x;
    int lane = tid & 31, w = tid >> 5;
    int warpM = w >> 1, warpN = w & 1;          // 4 x 2 warps: warp tile 32 x 64
    int g = lane >> 2, t = lane & 3;
    int rowBase = blockIdx.x * 128;

    float acc[2][8][4];
    #pragma unroll
    for (int i = 0; i < 2; i++)
        #pragma unroll
        for (int j = 0; j < 8; j++)
            #pragma unroll
            for (int q = 0; q < 4; q++) acc[i][j][q] = 0.f;

    for (int kt = 0; kt < NCHUNK; kt++) {
        int k0 = kt * 32;
        // stage A tile (128 rows x 32 halves) via 32-bit loads
        #pragma unroll
        for (int i = 0; i < 8; i++) {
            int idx = tid + i * 256;            // 0..2047
            int r = idx >> 4, u = idx & 15;     // u = half-pair index
            int k = k0 + 2 * u;
            unsigned v = 0;
            if (k < KDIM)
                v = *(const unsigned*)(g_Ah + (size_t)(rowBase + r) * KDIM + k);
            *(unsigned*)&As[r][2 * u] = v;
        }
        // stage W tile (32 k x 128 cols) fp32->fp16, transposed to [col][k]
        #pragma unroll
        for (int i = 0; i < 16; i++) {
            int idx = tid + i * 256;            // 0..4095
            int kk = idx >> 7, c = idx & 127;
            int k = k0 + kk;
            float v = (k < KDIM) ? W[k * 128 + c] : 0.f;
            Wst[c][kk] = __float2half_rn(v);
        }
        __syncthreads();
        #pragma unroll
        for (int ks = 0; ks < 2; ks++) {
            int kb = ks * 16;
            unsigned a[2][4], b[8][2];
            #pragma unroll
            for (int i = 0; i < 2; i++) {
                int r = warpM * 32 + i * 16 + g;
                a[i][0] = *(const unsigned*)&As[r][kb + 2 * t];
                a[i][1] = *(const unsigned*)&As[r + 8][kb + 2 * t];
                a[i][2] = *(const unsigned*)&As[r][kb + 2 * t + 8];
                a[i][3] = *(const unsigned*)&As[r + 8][kb + 2 * t + 8];
            }
            #pragma unroll
            for (int j = 0; j < 8; j++) {
                int c = warpN * 64 + j * 8 + g;
                b[j][0] = *(const unsigned*)&Wst[c][kb + 2 * t];
                b[j][1] = *(const unsigned*)&Wst[c][kb + 2 * t + 8];
            }
            #pragma unroll
            for (int i = 0; i < 2; i++)
                #pragma unroll
                for (int j = 0; j < 8; j++)
                    mma_f16(acc[i][j], a[i], b[j]);
        }
        __syncthreads();
    }

    // epilogue
    #pragma unroll
    for (int i = 0; i < 2; i++) {
        #pragma unroll
        for (int j = 0; j < 8; j++) {
            int col0 = warpN * 64 + j * 8 + 2 * t;
            #pragma unroll
            for (int half = 0; half < 2; half++) {
                int row = rowBase + warpM * 32 + i * 16 + g + half * 8;
                int n = row >> 5, bb = row & 31;
                #pragma unroll
                for (int q = 0; q < 2; q++) {
                    int col = col0 + q;
                    float v = acc[i][j][half * 2 + q] + bias[col];
                    v = 1.f / (1.f + __expf(-v));
                    if (col < UNITS) {
                        float h = hx[(size_t)bb * (NN*UNITS) + n*UNITS + col];
                        g_X0h[(size_t)n * NBF + bb*FF + 2 + col] = __float2half_rn(v * h);
                    } else {
                        g_U[(size_t)row * UNITS + (col - UNITS)] = v;
                    }
                }
            }
        }
    }
}

// ---------------- GEMM2 (fp16 mma): (256000 x 330) @ (330 x 64) ---------------
__global__ __launch_bounds__(256) void gemm2_kernel(
        const float* __restrict__ W, const float* __restrict__ bias,
        const float* __restrict__ hx, float* __restrict__ out) {
    __shared__ __half As [128][ASTR];
    __shared__ __half Wst[64][ASTR];

    int tid = threadIdx.x;
    int lane = tid & 31, w = tid >> 5;
    int warpM = w >> 1, warpN = w & 1;          // warp tile 32 x 32
    int g = lane >> 2, t = lane & 3;
    int rowBase = blockIdx.x * 128;

    float acc[2][4][4];
    #pragma unroll
    for (int i = 0; i < 2; i++)
        #pragma unroll
        for (int j = 0; j < 4; j++)
            #pragma unroll
            for (int q = 0; q < 4; q++) acc[i][j][q] = 0.f;

    for (int kt = 0; kt < NCHUNK; kt++) {
        int k0 = kt * 32;
        #pragma unroll
        for (int i = 0; i < 8; i++) {
            int idx = tid + i * 256;
            int r = idx >> 4, u = idx & 15;
            int k = k0 + 2 * u;
            unsigned v = 0;
            if (k < KDIM)
                v = *(const unsigned*)(g_Ah + (size_t)(rowBase + r) * KDIM + k);
            *(unsigned*)&As[r][2 * u] = v;
        }
        #pragma unroll
        for (int i = 0; i < 8; i++) {
            int idx = tid + i * 256;            // 0..2047
            int kk = idx >> 6, c = idx & 63;
            int k = k0 + kk;
            float v = (k < KDIM) ? W[k * 64 + c] : 0.f;
            Wst[c][kk] = __float2half_rn(v);
        }
        __syncthreads();
        #pragma unroll
        for (int ks = 0; ks < 2; ks++) {
            int kb = ks * 16;
            unsigned a[2][4], b[4][2];
            #pragma unroll
            for (int i = 0; i < 2; i++) {
                int r = warpM * 32 + i * 16 + g;
                a[i][0] = *(const unsigned*)&As[r][kb + 2 * t];
                a[i][1] = *(const unsigned*)&As[r + 8][kb + 2 * t];
                a[i][2] = *(const unsigned*)&As[r][kb + 2 * t + 8];
                a[i][3] = *(const unsigned*)&As[r + 8][kb + 2 * t + 8];
            }
            #pragma unroll
            for (int j = 0; j < 4; j++) {
                int c = warpN * 32 + j * 8 + g;
                b[j][0] = *(const unsigned*)&Wst[c][kb + 2 * t];
                b[j][1] = *(const unsigned*)&Wst[c][kb + 2 * t + 8];
            }
            #pragma unroll
            for (int i = 0; i < 2; i++)
                #pragma unroll
                for (int j = 0; j < 4; j++)
                    mma_f16(acc[i][j], a[i], b[j]);
        }
        __syncthreads();
    }

    #pragma unroll
    for (int i = 0; i < 2; i++) {
        #pragma unroll
        for (int j = 0; j < 4; j++) {
            int col0 = warpN * 32 + j * 8 + 2 * t;
            #pragma unroll
            for (int half = 0; half < 2; half++) {
                int row = rowBase + warpM * 32 + i * 16 + g + half * 8;
                int n = row >> 5, bb = row & 31;
                #pragma unroll
                for (int q = 0; q < 2; q++) {
                    int col = col0 + q;
                    float c = tanhf(acc[i][j][half * 2 + q] + bias[col]);
                    float u = g_U[(size_t)row * UNITS + col];
                    float h = hx[(size_t)bb * (NN*UNITS) + n*UNITS + col];
                    out[(size_t)bb * (NN*UNITS) + n*UNITS + col] = u * h + (1.f - u) * c;
                }
            }
        }
    }
}

// ---------------- launch -------------------------------------------------------
extern "C" void kernel_launch(void* const* d_in, const int* in_sizes, int n_in,
                              void* d_out, int out_size) {
    const float* inputs = (const float*)d_in[0];
    const float* hx     = (const float*)d_in[1];
    const float* W_ru   = (const float*)d_in[2];
    const float* b_ru   = (const float*)d_in[3];
    const float* W_c    = (const float*)d_in[4];
    const float* b_c    = (const float*)d_in[5];
    const int*   s0r    = (const int*)d_in[6];
    const int*   s0c    = (const int*)d_in[7];
    const float* s0v    = (const float*)d_in[8];
    const int*   s1r    = (const int*)d_in[9];
    const int*   s1c    = (const int*)d_in[10];
    const float* s1v    = (const float*)d_in[11];
    int E = in_sizes[6];
    float* out = (float*)d_out;

    // CSR build (both supports)
    csr_prep<<<(2*NN + 255)/256, 256>>>();
    csr_count<<<(E + 255)/256, 256>>>(s0r, s1r, E);
    csr_scan<<<2, 1024>>>();
    csr_scatter<<<(E + 255)/256, 256>>>(s0r, s0c, s0v, E, 0);
    csr_scatter<<<(E + 255)/256, 256>>>(s1r, s1c, s1v, E, 1);

    dim3 spmmGrid(NN, 2);

    // gconv #1 (gates)
    build_x0<<<(NN*NBF)/256, 256>>>(inputs, hx);
    spmm_h<<<spmmGrid, 256>>>();
    chebpack_h<<<NN, 256>>>();
    gemm1_kernel<<<(NN*BB)/128, 256>>>(W_ru, b_ru, hx);   // writes state = r*hx into g_X0h

    // gconv #2 (candidate) + final combine
    spmm_h<<<spmmGrid, 256>>>();
    chebpack_h<<<NN, 256>>>();
    gemm2_kernel<<<(NN*BB)/128, 256>>>(W_c, b_c, hx, out);
}

// round 10
// speedup vs baseline: 2.5228x; 1.3681x over previous
#include <cuda_runtime.h>
#include <cuda_fp16.h>
#include <math.h>

// Problem constants (fixed by the dataset)
#define NN    8000
#define BB    32
#define FF    66            // input_dim(2) + units(64)
#define NBF   (BB*FF)       // 2112
#define MM    5             // num diffusion matrices = 2*K+1
#define KDIM  (FF*MM)       // 330
#define KPAD  336           // 21 * 16
#define ASTR  344           // smem k-stride in halves (conflict-free frag loads)
#define UNITS 64
#define EMAX  64000
#define VEC   (NBF/8)       // 264 uint4 (8 halves) per node row

// ---------------- scratch (static device globals; no cudaMalloc allowed) ------
__device__ __align__(16) __half g_X0h [NN*NBF];             // (N, B, F) fp16
__device__ __align__(16) __half g_X1ah[NN*NBF];             // S0 @ x0
__device__ __align__(16) __half g_X1bh[NN*NBF];             // S1 @ x0
__device__ float g_U  [(size_t)NN*BB*UNITS];                // update gate u (fp32)
__device__ int   g_ptr0[NN+1], g_ptr1[NN+1];
__device__ int   g_cidx0[EMAX], g_cidx1[EMAX];
__device__ float g_cval0[EMAX], g_cval1[EMAX];
__device__ int   g_cnt[2*NN];
__device__ int   g_cur[2*NN];

// ---------------- CSR build ---------------------------------------------------
__global__ void csr_prep() {
    int i = blockIdx.x * blockDim.x + threadIdx.x;
    if (i < 2*NN) { g_cnt[i] = 0; g_cur[i] = 0; }
}

__global__ void csr_count(const int* __restrict__ r0, const int* __restrict__ r1, int E) {
    int e = blockIdx.x * blockDim.x + threadIdx.x;
    if (e < E) {
        atomicAdd(&g_cnt[r0[e]], 1);
        atomicAdd(&g_cnt[NN + r1[e]], 1);
    }
}

__global__ void csr_scan() {
    int s = blockIdx.x;
    const int* cnt = g_cnt + s * NN;
    int* ptr = s ? g_ptr1 : g_ptr0;
    __shared__ int sm[1024];
    __shared__ int carry;
    if (threadIdx.x == 0) carry = 0;
    __syncthreads();
    for (int base = 0; base < NN; base += 1024) {
        int i = base + threadIdx.x;
        int v = (i < NN) ? cnt[i] : 0;
        sm[threadIdx.x] = v;
        __syncthreads();
        int c0 = carry;
        for (int off = 1; off < 1024; off <<= 1) {
            int t = (threadIdx.x >= (unsigned)off) ? sm[threadIdx.x - off] : 0;
            __syncthreads();
            sm[threadIdx.x] += t;
            __syncthreads();
        }
        if (i < NN) ptr[i] = c0 + sm[threadIdx.x] - v;
        __syncthreads();
        if (threadIdx.x == 1023) carry = c0 + sm[1023];
        __syncthreads();
    }
    if (threadIdx.x == 0) ptr[NN] = carry;
}

// merged: blockIdx.y selects support
__global__ void csr_scatter2(const int* __restrict__ r0c, const int* __restrict__ c0c,
                             const float* __restrict__ v0c,
                             const int* __restrict__ r1c, const int* __restrict__ c1c,
                             const float* __restrict__ v1c, int E) {
    int e = blockIdx.x * blockDim.x + threadIdx.x;
    if (e >= E) return;
    int s = blockIdx.y;
    const int*   r = s ? r1c : r0c;
    const int*   c = s ? c1c : c0c;
    const float* v = s ? v1c : v0c;
    int row = r[e];
    int* cur = g_cur + s * NN;
    const int* ptr = s ? g_ptr1 : g_ptr0;
    int* ci = s ? g_cidx1 : g_cidx0;
    float* cv = s ? g_cval1 : g_cval0;
    int p = ptr[row] + atomicAdd(&cur[row], 1);
    ci[p] = c[e];
    cv[p] = v[e];
}

// ---------------- build x0 (N,B,F) fp16 from inputs (B,N,2) + hx (B,N,64) ----
__global__ void build_x0(const float* __restrict__ inputs, const float* __restrict__ hx) {
    int idx = blockIdx.x * blockDim.x + threadIdx.x;   // over NN*NBF
    int n = idx / NBF;
    int rem = idx - n * NBF;
    int b = rem / FF;
    int f = rem - b * FF;
    float v;
    if (f < 2) v = inputs[(size_t)b * (NN*2) + n*2 + f];
    else       v = hx[(size_t)b * (NN*UNITS) + n*UNITS + (f-2)];
    g_X0h[idx] = __float2half_rn(v);
}

// ---------------- fma helper: acc[8] += w * unpack(uint4 of 8 halves) --------
__device__ __forceinline__ void hfma8(float* acc, uint4 v, float w) {
    const __half2* h = (const __half2*)&v;
    #pragma unroll
    for (int p = 0; p < 4; p++) {
        float2 f = __half22float2(h[p]);
        acc[2*p]   += w * f.x;
        acc[2*p+1] += w * f.y;
    }
}

// ---------------- spmm: y = S @ x0 (both supports), one block per (node, s) --
__global__ void spmm_h() {
    int s = blockIdx.y;
    const int*   ptr = s ? g_ptr1  : g_ptr0;
    const int*   ci  = s ? g_cidx1 : g_cidx0;
    const float* cv  = s ? g_cval1 : g_cval0;
    __half*      y   = s ? g_X1bh  : g_X1ah;
    const uint4* X   = (const uint4*)g_X0h;
    int n = blockIdx.x;
    int beg = ptr[n], end = ptr[n+1];
    for (int i = threadIdx.x; i < VEC; i += blockDim.x) {
        float acc[8];
        #pragma unroll
        for (int j = 0; j < 8; j++) acc[j] = 0.f;
        for (int e = beg; e < end; e++) {
            uint4 v = X[(size_t)ci[e] * VEC + i];
            hfma8(acc, v, cv[e]);
        }
        uint4 o;
        __half2* oh = (__half2*)&o;
        #pragma unroll
        for (int p = 0; p < 4; p++)
            oh[p] = __floats2half2_rn(acc[2*p], acc[2*p+1]);
        ((uint4*)y)[(size_t)n * VEC + i] = o;
    }
}

// ---------------- fp16 mma helper ---------------------------------------------
__device__ __forceinline__ void mma_f16(float* d, const unsigned* a, const unsigned* b) {
    asm volatile(
        "mma.sync.aligned.m16n8k16.row.col.f32.f16.f16.f32 "
        "{%0,%1,%2,%3}, {%4,%5,%6,%7}, {%8,%9}, {%0,%1,%2,%3};\n"
        : "+f"(d[0]), "+f"(d[1]), "+f"(d[2]), "+f"(d[3])
        : "r"(a[0]), "r"(a[1]), "r"(a[2]), "r"(a[3]), "r"(b[0]), "r"(b[1]));
}

// =====================================================================
// Fused gconv kernel: per block = 4 nodes (128 GEMM rows).
//   phase 1: build packed A tile (cheb gather) directly in smem (fp16)
//   phase 2: stage W (fp32->fp16, [col][k]) in smem
//   phase 3: fp16 MMA k-loop entirely from smem; fused epilogue
// NCOLS = 128 (gates, sigmoid, GCONV==1) or 64 (candidate, tanh, GCONV==2)
// =====================================================================
template<int NCOLS, int GCONV>
__global__ __launch_bounds__(512) void fused_gconv(
        const float* __restrict__ W, const float* __restrict__ bias,
        const float* __restrict__ hx, float* __restrict__ out) {
    extern __shared__ __half smem[];
    __half* As = smem;                 // [128][ASTR]
    __half* Ws = smem + 128 * ASTR;    // [NCOLS][ASTR]

    int tid = threadIdx.x;
    const uint4* X0 = (const uint4*)g_X0h;
    const uint4* XA = (const uint4*)g_X1ah;
    const uint4* XB = (const uint4*)g_X1bh;

    // ---- phase 1: cheb gather + pack A into smem ----
    for (int task = tid; task < 4 * VEC; task += 512) {
        int ln = task / VEC;
        int i  = task - ln * VEC;
        int n  = blockIdx.x * 4 + ln;
        int b0 = g_ptr0[n], e0 = g_ptr0[n+1];
        int b1 = g_ptr1[n], e1 = g_ptr1[n+1];
        uint4 v0 = X0[(size_t)n * VEC + i];
        uint4 va = XA[(size_t)n * VEC + i];
        uint4 vb = XB[(size_t)n * VEC + i];
        float a2[8], a4[8];
        {
            const __half2* h = (const __half2*)&v0;
            #pragma unroll
            for (int p = 0; p < 4; p++) {
                float2 f = __half22float2(h[p]);
                a2[2*p] = -f.x; a2[2*p+1] = -f.y;
                a4[2*p] = -f.x; a4[2*p+1] = -f.y;
            }
        }
        for (int e = b0; e < e0; e++)
            hfma8(a2, XA[(size_t)g_cidx0[e] * VEC + i], 2.f * g_cval0[e]);
        for (int e = b1; e < e1; e++)
            hfma8(a4, XB[(size_t)g_cidx1[e] * VEC + i], 2.f * g_cval1[e]);

        const __half* h0 = (const __half*)&v0;
        const __half* ha = (const __half*)&va;
        const __half* hb = (const __half*)&vb;
        #pragma unroll
        for (int j = 0; j < 8; j++) {
            int h = i * 8 + j;
            int b = h / FF, f = h - b * FF;
            __half* dst = &As[(ln * 32 + b) * ASTR + f * MM];
            dst[0] = h0[j];
            dst[1] = ha[j];
            dst[2] = __float2half_rn(a2[j]);
            dst[3] = hb[j];
            dst[4] = __float2half_rn(a4[j]);
        }
    }
    // zero A k-pad [330, 336)
    for (int idx = tid; idx < 128 * (KPAD - KDIM); idx += 512) {
        int r = idx / (KPAD - KDIM), k = KDIM + idx % (KPAD - KDIM);
        As[r * ASTR + k] = __float2half_rn(0.f);
    }
    // ---- phase 2: stage W transposed [col][k] ----
    for (int idx = tid; idx < KPAD * NCOLS; idx += 512) {
        int k = idx / NCOLS, c = idx - k * NCOLS;
        float v = (k < KDIM) ? W[k * NCOLS + c] : 0.f;
        Ws[c * ASTR + k] = __float2half_rn(v);
    }
    __syncthreads();

    // ---- phase 3: GEMM (16 warps; warp tile 16 x (NCOLS/2)) ----
    int lane = tid & 31, w = tid >> 5;
    int warpM = w & 7, warpN = w >> 3;      // 8 x 2 warps
    int g = lane >> 2, t = lane & 3;
    const int NJ = NCOLS / 16;              // 8 or 4 n-tiles of 8
    int rowBase = blockIdx.x * 128;

    float acc[NCOLS/16][4];
    #pragma unroll
    for (int j = 0; j < NJ; j++)
        #pragma unroll
        for (int q = 0; q < 4; q++) acc[j][q] = 0.f;

    int rA = (warpM * 16 + g) * ASTR;
    #pragma unroll 3
    for (int kt = 0; kt < KPAD / 16; kt++) {
        int kb = kt * 16;
        unsigned a[4];
        a[0] = *(const unsigned*)&As[rA + kb + 2*t];
        a[1] = *(const unsigned*)&As[rA + 8 * ASTR + kb + 2*t];
        a[2] = *(const unsigned*)&As[rA + kb + 2*t + 8];
        a[3] = *(const unsigned*)&As[rA + 8 * ASTR + kb + 2*t + 8];
        #pragma unroll
        for (int j = 0; j < NJ; j++) {
            unsigned b[2];
            int c = warpN * (NCOLS/2) + j * 8 + g;
            b[0] = *(const unsigned*)&Ws[c * ASTR + kb + 2*t];
            b[1] = *(const unsigned*)&Ws[c * ASTR + kb + 2*t + 8];
            mma_f16(acc[j], a, b);
        }
    }

    // ---- epilogue ----
    #pragma unroll
    for (int j = 0; j < NJ; j++) {
        int col0 = warpN * (NCOLS/2) + j * 8 + 2 * t;
        #pragma unroll
        for (int half = 0; half < 2; half++) {
            int row = rowBase + warpM * 16 + g + half * 8;
            int n = row >> 5, bb = row & 31;
            #pragma unroll
            for (int q = 0; q < 2; q++) {
                int col = col0 + q;
                float v = acc[j][half * 2 + q] + bias[col];
                if (GCONV == 1) {
                    v = 1.f / (1.f + __expf(-v));
                    if (col < UNITS) {
                        float h = hx[(size_t)bb * (NN*UNITS) + n*UNITS + col];
                        g_X0h[(size_t)n * NBF + bb*FF + 2 + col] = __float2half_rn(v * h);
                    } else {
                        g_U[(size_t)row * UNITS + (col - UNITS)] = v;
                    }
                } else {
                    float c = tanhf(v);
                    float u = g_U[(size_t)row * UNITS + col];
                    float h = hx[(size_t)bb * (NN*UNITS) + n*UNITS + col];
                    out[(size_t)bb * (NN*UNITS) + n*UNITS + col] = u * h + (1.f - u) * c;
                }
            }
        }
    }
}

// ---------------- launch -------------------------------------------------------
extern "C" void kernel_launch(void* const* d_in, const int* in_sizes, int n_in,
                              void* d_out, int out_size) {
    const float* inputs = (const float*)d_in[0];
    const float* hx     = (const float*)d_in[1];
    const float* W_ru   = (const float*)d_in[2];
    const float* b_ru   = (const float*)d_in[3];
    const float* W_c    = (const float*)d_in[4];
    const float* b_c    = (const float*)d_in[5];
    const int*   s0r    = (const int*)d_in[6];
    const int*   s0c    = (const int*)d_in[7];
    const float* s0v    = (const float*)d_in[8];
    const int*   s1r    = (const int*)d_in[9];
    const int*   s1c    = (const int*)d_in[10];
    const float* s1v    = (const float*)d_in[11];
    int E = in_sizes[6];
    float* out = (float*)d_out;

    const int smem1 = (128 + 128) * ASTR * 2;   // 176128 B
    const int smem2 = (128 + 64)  * ASTR * 2;   // 132096 B
    cudaFuncSetAttribute(fused_gconv<128,1>, cudaFuncAttributeMaxDynamicSharedMemorySize, smem1);
    cudaFuncSetAttribute(fused_gconv<64,2>,  cudaFuncAttributeMaxDynamicSharedMemorySize, smem2);

    // CSR build (both supports)
    csr_prep<<<(2*NN + 255)/256, 256>>>();
    csr_count<<<(E + 255)/256, 256>>>(s0r, s1r, E);
    csr_scan<<<2, 1024>>>();
    dim3 scGrid((E + 255)/256, 2);
    csr_scatter2<<<scGrid, 256>>>(s0r, s0c, s0v, s1r, s1c, s1v, E);

    dim3 spmmGrid(NN, 2);

    // gconv #1 (gates) — launch index 5 is spmm_h (profiled slot)
    build_x0<<<(NN*NBF)/256, 256>>>(inputs, hx);
    spmm_h<<<spmmGrid, 256>>>();
    fused_gconv<128,1><<<NN/4, 512, smem1>>>(W_ru, b_ru, hx, out);

    // gconv #2 (candidate) + final combine
    spmm_h<<<spmmGrid, 256>>>();
    fused_gconv<64,2><<<NN/4, 512, smem2>>>(W_c, b_c, hx, out);
}

// round 11
// speedup vs baseline: 2.6725x; 1.0593x over previous
#include <cuda_runtime.h>
#include <cuda_fp16.h>
#include <math.h>

// Problem constants (fixed by the dataset)
#define NN    8000
#define BB    32
#define FF    66            // input_dim(2) + units(64)
#define NBF   (BB*FF)       // 2112
#define MM    5             // num diffusion matrices = 2*K+1
#define KDIM  (FF*MM)       // 330
#define KPAD  336           // 21 * 16
#define ASTR  344           // smem k-stride in halves (conflict-free frag loads)
#define UNITS 64
#define EMAX  64000
#define VEC   (NBF/8)       // 264 uint4 (8 halves) per node row
#define MROWS 64            // GEMM rows per tile = 2 nodes
#define NTILES (NN*BB/MROWS)   // 4000
#define PGRID 152           // persistent blocks (1/SM on GB300)

// ---------------- scratch (static device globals; no cudaMalloc allowed) ------
__device__ __align__(16) __half g_X0h [NN*NBF];             // (N, B, F) fp16
__device__ __align__(16) __half g_X1ah[NN*NBF];             // S0 @ x0
__device__ __align__(16) __half g_X1bh[NN*NBF];             // S1 @ x0
__device__ float g_U  [(size_t)NN*BB*UNITS];                // update gate u (fp32)
__device__ int   g_ptr0[NN+1], g_ptr1[NN+1];
__device__ int   g_cidx0[EMAX], g_cidx1[EMAX];
__device__ float g_cval0[EMAX], g_cval1[EMAX];
__device__ int   g_cnt[2*NN];   // zero at start of each call (self-cleaning)
__device__ int   g_cur[2*NN];   // zeroed by csr_count each call

// ---------------- CSR build (self-cleaning, 3 launches) -----------------------
// launch 0: zero g_cur + histogram rows into g_cnt (g_cnt is zero on entry:
//           zero-initialized at load, reset by csr_scan at every call)
__global__ void csr_count(const int* __restrict__ r0, const int* __restrict__ r1, int E) {
    int e = blockIdx.x * blockDim.x + threadIdx.x;
    if (e < 2*NN) g_cur[e] = 0;
    if (e < E) {
        atomicAdd(&g_cnt[r0[e]], 1);
        atomicAdd(&g_cnt[NN + r1[e]], 1);
    }
}

// launch 1: exclusive scan of counts -> ptr; resets g_cnt to 0 for next call
__global__ void csr_scan() {
    int s = blockIdx.x;
    int* cnt = g_cnt + s * NN;
    int* ptr = s ? g_ptr1 : g_ptr0;
    __shared__ int sm[1024];
    __shared__ int carry;
    if (threadIdx.x == 0) carry = 0;
    __syncthreads();
    for (int base = 0; base < NN; base += 1024) {
        int i = base + threadIdx.x;
        int v = (i < NN) ? cnt[i] : 0;
        if (i < NN) cnt[i] = 0;          // self-clean for next call
        sm[threadIdx.x] = v;
        __syncthreads();
        int c0 = carry;
        for (int off = 1; off < 1024; off <<= 1) {
            int t = (threadIdx.x >= (unsigned)off) ? sm[threadIdx.x - off] : 0;
            __syncthreads();
            sm[threadIdx.x] += t;
            __syncthreads();
        }
        if (i < NN) ptr[i] = c0 + sm[threadIdx.x] - v;
        __syncthreads();
        if (threadIdx.x == 1023) carry = c0 + sm[1023];
        __syncthreads();
    }
    if (threadIdx.x == 0) ptr[NN] = carry;
}

// launch 2: CSR scatter (both supports) fused with build_x0
__global__ void scatter_build(const int* __restrict__ r0c, const int* __restrict__ c0c,
                              const float* __restrict__ v0c,
                              const int* __restrict__ r1c, const int* __restrict__ c1c,
                              const float* __restrict__ v1c, int E,
                              const float* __restrict__ inputs, const float* __restrict__ hx) {
    long long idx = (long long)blockIdx.x * blockDim.x + threadIdx.x;
    if (idx < 2*E) {
        int s = idx >= E;
        int e = (int)(s ? idx - E : idx);
        const int*   r = s ? r1c : r0c;
        const int*   c = s ? c1c : c0c;
        const float* v = s ? v1c : v0c;
        int row = r[e];
        int p = (s ? g_ptr1 : g_ptr0)[row] + atomicAdd(&g_cur[s*NN + row], 1);
        (s ? g_cidx1 : g_cidx0)[p] = c[e];
        (s ? g_cval1 : g_cval0)[p] = v[e];
        return;
    }
    long long i = idx - 2*E;
    if (i < (long long)NN * NBF) {
        int n = (int)(i / NBF);
        int rem = (int)(i - (long long)n * NBF);
        int b = rem / FF;
        int f = rem - b * FF;
        float v;
        if (f < 2) v = inputs[(size_t)b * (NN*2) + n*2 + f];
        else       v = hx[(size_t)b * (NN*UNITS) + n*UNITS + (f-2)];
        g_X0h[i] = __float2half_rn(v);
    }
}

// ---------------- fma helper: acc[8] += w * unpack(uint4 of 8 halves) --------
__device__ __forceinline__ void hfma8(float* acc, uint4 v, float w) {
    const __half2* h = (const __half2*)&v;
    #pragma unroll
    for (int p = 0; p < 4; p++) {
        float2 f = __half22float2(h[p]);
        acc[2*p]   += w * f.x;
        acc[2*p+1] += w * f.y;
    }
}

// ---------------- spmm: y = S @ x0 (both supports), one block per (node, s) --
__global__ void spmm_h() {
    int s = blockIdx.y;
    const int*   ptr = s ? g_ptr1  : g_ptr0;
    const int*   ci  = s ? g_cidx1 : g_cidx0;
    const float* cv  = s ? g_cval1 : g_cval0;
    __half*      y   = s ? g_X1bh  : g_X1ah;
    const uint4* X   = (const uint4*)g_X0h;
    int n = blockIdx.x;
    int beg = ptr[n], end = ptr[n+1];
    for (int i = threadIdx.x; i < VEC; i += blockDim.x) {
        float acc[8];
        #pragma unroll
        for (int j = 0; j < 8; j++) acc[j] = 0.f;
        for (int e = beg; e < end; e++) {
            uint4 v = X[(size_t)ci[e] * VEC + i];
            hfma8(acc, v, cv[e]);
        }
        uint4 o;
        __half2* oh = (__half2*)&o;
        #pragma unroll
        for (int p = 0; p < 4; p++)
            oh[p] = __floats2half2_rn(acc[2*p], acc[2*p+1]);
        ((uint4*)y)[(size_t)n * VEC + i] = o;
    }
}

// ---------------- fp16 mma helper ---------------------------------------------
__device__ __forceinline__ void mma_f16(float* d, const unsigned* a, const unsigned* b) {
    asm volatile(
        "mma.sync.aligned.m16n8k16.row.col.f32.f16.f16.f32 "
        "{%0,%1,%2,%3}, {%4,%5,%6,%7}, {%8,%9}, {%0,%1,%2,%3};\n"
        : "+f"(d[0]), "+f"(d[1]), "+f"(d[2]), "+f"(d[3])
        : "r"(a[0]), "r"(a[1]), "r"(a[2]), "r"(a[3]), "r"(b[0]), "r"(b[1]));
}

// ---------------- gather one 64-row A tile (2 nodes) into smem ----------------
__device__ __forceinline__ void gather_tile(int t, __half* As, int tid) {
    const uint4* X0 = (const uint4*)g_X0h;
    const uint4* XA = (const uint4*)g_X1ah;
    const uint4* XB = (const uint4*)g_X1bh;
    for (int task = tid; task < 2 * VEC; task += 512) {
        int ln = (task >= VEC) ? 1 : 0;
        int i  = task - ln * VEC;
        int n  = t * 2 + ln;
        int b0 = g_ptr0[n], e0 = g_ptr0[n+1];
        int b1 = g_ptr1[n], e1 = g_ptr1[n+1];
        uint4 v0 = X0[(size_t)n * VEC + i];
        uint4 va = XA[(size_t)n * VEC + i];
        uint4 vb = XB[(size_t)n * VEC + i];
        float a2[8], a4[8];
        {
            const __half2* h = (const __half2*)&v0;
            #pragma unroll
            for (int p = 0; p < 4; p++) {
                float2 f = __half22float2(h[p]);
                a2[2*p] = -f.x; a2[2*p+1] = -f.y;
                a4[2*p] = -f.x; a4[2*p+1] = -f.y;
            }
        }
        for (int e = b0; e < e0; e++)
            hfma8(a2, XA[(size_t)g_cidx0[e] * VEC + i], 2.f * g_cval0[e]);
        for (int e = b1; e < e1; e++)
            hfma8(a4, XB[(size_t)g_cidx1[e] * VEC + i], 2.f * g_cval1[e]);

        const __half* h0 = (const __half*)&v0;
        const __half* ha = (const __half*)&va;
        const __half* hb = (const __half*)&vb;
        #pragma unroll
        for (int j = 0; j < 8; j++) {
            int h = i * 8 + j;
            int b = h / FF, f = h - b * FF;
            __half* dst = &As[(ln * 32 + b) * ASTR + f * MM];
            dst[0] = h0[j];
            dst[1] = ha[j];
            dst[2] = __float2half_rn(a2[j]);
            dst[3] = hb[j];
            dst[4] = __float2half_rn(a4[j]);
        }
    }
}

// =====================================================================
// Persistent fused gconv: W staged once per block; loop 64-row tiles
// with double-buffered A (gather t+1 overlaps MMA on t).
// =====================================================================
template<int NCOLS, int GCONV>
__global__ __launch_bounds__(512) void fused_gconv_p(
        const float* __restrict__ W, const float* __restrict__ bias,
        const float* __restrict__ hx, float* __restrict__ out) {
    extern __shared__ __half smem[];
    __half* Ws = smem;                         // [NCOLS][ASTR]
    __half* A0 = smem + NCOLS * ASTR;          // [64][ASTR]
    __half* A1 = A0 + MROWS * ASTR;

    int tid = threadIdx.x;

    // stage W once: [col][k], fp32 -> fp16
    for (int idx = tid; idx < KPAD * NCOLS; idx += 512) {
        int k = idx / NCOLS, c = idx - k * NCOLS;
        float v = (k < KDIM) ? W[k * NCOLS + c] : 0.f;
        Ws[c * ASTR + k] = __float2half_rn(v);
    }
    // zero A k-pads of both buffers once (gather never touches k >= KDIM)
    for (int idx = tid; idx < MROWS * (KPAD - KDIM); idx += 512) {
        int r = idx / (KPAD - KDIM), k = KDIM + idx % (KPAD - KDIM);
        A0[r * ASTR + k] = __ushort_as_half((unsigned short)0);
        A1[r * ASTR + k] = __ushort_as_half((unsigned short)0);
    }

    int lane = tid & 31, w = tid >> 5;
    int warpM = w & 3, warpN = w >> 2;        // 4 x 4 warps: 16 rows x NCOLS/4 cols
    int g = lane >> 2, tq = lane & 3;
    constexpr int NJ = NCOLS / 32;            // n-tiles of 8 per warp (4 or 2)

    int it = 0;
    for (int t = blockIdx.x; t < NTILES; t += PGRID, ++it) {
        __half* cur = (it & 1) ? A1 : A0;
        __half* nxt = (it & 1) ? A0 : A1;
        if (it == 0) {
            gather_tile(t, cur, tid);
            __syncthreads();
        }
        int tn = t + PGRID;
        if (tn < NTILES) gather_tile(tn, nxt, tid);

        // ---- MMA on cur ----
        float acc[NJ][4];
        #pragma unroll
        for (int j = 0; j < NJ; j++)
            #pragma unroll
            for (int q = 0; q < 4; q++) acc[j][q] = 0.f;

        int rA = (warpM * 16 + g) * ASTR;
        #pragma unroll
        for (int kt = 0; kt < KPAD / 16; kt++) {
            int kb = kt * 16;
            unsigned a[4];
            a[0] = *(const unsigned*)&cur[rA + kb + 2*tq];
            a[1] = *(const unsigned*)&cur[rA + 8 * ASTR + kb + 2*tq];
            a[2] = *(const unsigned*)&cur[rA + kb + 2*tq + 8];
            a[3] = *(const unsigned*)&cur[rA + 8 * ASTR + kb + 2*tq + 8];
            #pragma unroll
            for (int j = 0; j < NJ; j++) {
                unsigned b[2];
                int c = warpN * (NCOLS/4) + j * 8 + g;
                b[0] = *(const unsigned*)&Ws[c * ASTR + kb + 2*tq];
                b[1] = *(const unsigned*)&Ws[c * ASTR + kb + 2*tq + 8];
                mma_f16(acc[j], a, b);
            }
        }

        // ---- epilogue for tile t ----
        #pragma unroll
        for (int j = 0; j < NJ; j++) {
            int col0 = warpN * (NCOLS/4) + j * 8 + 2 * tq;
            #pragma unroll
            for (int half = 0; half < 2; half++) {
                int row = t * MROWS + warpM * 16 + g + half * 8;
                int n = row >> 5, bb = row & 31;
                #pragma unroll
                for (int q = 0; q < 2; q++) {
                    int col = col0 + q;
                    float v = acc[j][half * 2 + q] + bias[col];
                    if (GCONV == 1) {
                        v = 1.f / (1.f + __expf(-v));
                        if (col < UNITS) {
                            float h = hx[(size_t)bb * (NN*UNITS) + n*UNITS + col];
                            g_X0h[(size_t)n * NBF + bb*FF + 2 + col] = __float2half_rn(v * h);
                        } else {
                            g_U[(size_t)row * UNITS + (col - UNITS)] = v;
                        }
                    } else {
                        float c = tanhf(v);
                        float u = g_U[(size_t)row * UNITS + col];
                        float h = hx[(size_t)bb * (NN*UNITS) + n*UNITS + col];
                        out[(size_t)bb * (NN*UNITS) + n*UNITS + col] = u * h + (1.f - u) * c;
                    }
                }
            }
        }
        __syncthreads();
    }
}

// ---------------- launch -------------------------------------------------------
extern "C" void kernel_launch(void* const* d_in, const int* in_sizes, int n_in,
                              void* d_out, int out_size) {
    const float* inputs = (const float*)d_in[0];
    const float* hx     = (const float*)d_in[1];
    const float* W_ru   = (const float*)d_in[2];
    const float* b_ru   = (const float*)d_in[3];
    const float* W_c    = (const float*)d_in[4];
    const float* b_c    = (const float*)d_in[5];
    const int*   s0r    = (const int*)d_in[6];
    const int*   s0c    = (const int*)d_in[7];
    const float* s0v    = (const float*)d_in[8];
    const int*   s1r    = (const int*)d_in[9];
    const int*   s1c    = (const int*)d_in[10];
    const float* s1v    = (const float*)d_in[11];
    int E = in_sizes[6];
    float* out = (float*)d_out;

    const int smem1 = (128 + 2 * MROWS) * ASTR * 2;   // 176128 B
    const int smem2 = (64  + 2 * MROWS) * ASTR * 2;   // 132096 B
    cudaFuncSetAttribute(fused_gconv_p<128,1>, cudaFuncAttributeMaxDynamicSharedMemorySize, smem1);
    cudaFuncSetAttribute(fused_gconv_p<64,2>,  cudaFuncAttributeMaxDynamicSharedMemorySize, smem2);

    // 0: histogram (+ zero g_cur); g_cnt zero on entry (reset by csr_scan)
    csr_count<<<(E + 255)/256, 256>>>(s0r, s1r, E);
    // 1: scan + self-clean g_cnt
    csr_scan<<<2, 1024>>>();
    // 2: scatter both supports + build x0 (fp16)
    long long tasks = 2LL*E + (long long)NN*NBF;
    scatter_build<<<(unsigned)((tasks + 255)/256), 256>>>(s0r, s0c, s0v, s1r, s1c, s1v, E,
                                                          inputs, hx);

    dim3 spmmGrid(NN, 2);

    // 3 (profiled slot): spmm for gconv #1
    spmm_h<<<spmmGrid, 256>>>();
    // 4: persistent fused gconv #1 (gates; writes state=r*hx into g_X0h, u into g_U)
    fused_gconv_p<128,1><<<PGRID, 512, smem1>>>(W_ru, b_ru, hx, out);

    // 5: spmm for gconv #2
    spmm_h<<<spmmGrid, 256>>>();
    // 6: persistent fused gconv #2 (candidate + final combine)
    fused_gconv_p<64,2><<<PGRID, 512, smem2>>>(W_c, b_c, hx, out);
}

// round 13
// speedup vs baseline: 3.0790x; 1.1521x over previous
#include <cuda_runtime.h>
#include <cuda_fp16.h>
#include <math.h>

// Problem constants (fixed by the dataset)
#define NN    8000
#define BB    32
#define FF    66            // input_dim(2) + units(64)
#define FFP   72            // padded F (octet-aligned; pads are zero)
#define NBFP  (BB*FFP)      // 2304
#define MM    5             // num diffusion matrices = 2*K+1
#define KDIMP (MM*FFP)      // 360 (planar K: k' = m*72 + f)
#define KPADP 368           // 23 * 16
#define ASTR  376           // smem k-stride in halves (47 uint4; conflict-free frags)
#define UNITS 64
#define EMAX  64000
#define VECP  (NBFP/8)      // 288 uint4 per node row
#define OCT   (FFP/8)       // 9 octets per batch lane
#define MROWS 64            // GEMM rows per tile = 2 nodes
#define NTILES (NN*BB/MROWS)   // 4000
#define PGRID 152           // persistent blocks

// ---------------- scratch (static device globals) -----------------------------
__device__ __align__(16) __half g_X0h [NN*NBFP];   // (N, B, Fp) fp16
__device__ __align__(16) __half g_X1ah[NN*NBFP];   // S0 @ x0
__device__ __align__(16) __half g_X1bh[NN*NBFP];   // S1 @ x0
__device__ __align__(16) __half g_X2ah[NN*NBFP];   // 2 S0 x1a - x0
__device__ __align__(16) __half g_X2bh[NN*NBFP];   // 2 S1 x1b - x0
__device__ float g_U  [(size_t)NN*BB*UNITS];       // update gate u (fp32)
__device__ int   g_ptr0[NN+1], g_ptr1[NN+1];
__device__ int   g_cidx0[EMAX], g_cidx1[EMAX];
__device__ float g_cval0[EMAX], g_cval1[EMAX];
__device__ int   g_cnt[2*NN];   // zero at start of each call (self-cleaning)
__device__ int   g_cur[2*NN];

// ---------------- CSR build (self-cleaning) ------------------------------------
__global__ void csr_count(const int* __restrict__ r0, const int* __restrict__ r1, int E) {
    int e = blockIdx.x * blockDim.x + threadIdx.x;
    if (e < 2*NN) g_cur[e] = 0;
    if (e < E) {
        atomicAdd(&g_cnt[r0[e]], 1);
        atomicAdd(&g_cnt[NN + r1[e]], 1);
    }
}

__global__ void csr_scan() {
    int s = blockIdx.x;
    int* cnt = g_cnt + s * NN;
    int* ptr = s ? g_ptr1 : g_ptr0;
    __shared__ int sm[1024];
    __shared__ int carry;
    if (threadIdx.x == 0) carry = 0;
    __syncthreads();
    for (int base = 0; base < NN; base += 1024) {
        int i = base + threadIdx.x;
        int v = (i < NN) ? cnt[i] : 0;
        if (i < NN) cnt[i] = 0;          // self-clean for next call
        sm[threadIdx.x] = v;
        __syncthreads();
        int c0 = carry;
        for (int off = 1; off < 1024; off <<= 1) {
            int t = (threadIdx.x >= (unsigned)off) ? sm[threadIdx.x - off] : 0;
            __syncthreads();
            sm[threadIdx.x] += t;
            __syncthreads();
        }
        if (i < NN) ptr[i] = c0 + sm[threadIdx.x] - v;
        __syncthreads();
        if (threadIdx.x == 1023) carry = c0 + sm[1023];
        __syncthreads();
    }
    if (threadIdx.x == 0) ptr[NN] = carry;
}

// scatter (both supports) fused with build_x0 (padded fp16 layout)
__global__ void scatter_build(const int* __restrict__ r0c, const int* __restrict__ c0c,
                              const float* __restrict__ v0c,
                              const int* __restrict__ r1c, const int* __restrict__ c1c,
                              const float* __restrict__ v1c, int E,
                              const float* __restrict__ inputs, const float* __restrict__ hx) {
    long long idx = (long long)blockIdx.x * blockDim.x + threadIdx.x;
    if (idx < 2*E) {
        int s = idx >= E;
        int e = (int)(s ? idx - E : idx);
        const int*   r = s ? r1c : r0c;
        const int*   c = s ? c1c : c0c;
        const float* v = s ? v1c : v0c;
        int row = r[e];
        int p = (s ? g_ptr1 : g_ptr0)[row] + atomicAdd(&g_cur[s*NN + row], 1);
        (s ? g_cidx1 : g_cidx0)[p] = c[e];
        (s ? g_cval1 : g_cval0)[p] = v[e];
        return;
    }
    long long i = idx - 2*E;
    if (i < (long long)NN * NBFP) {
        int n = (int)(i / NBFP);
        int rem = (int)(i - (long long)n * NBFP);
        int b = rem / FFP;
        int f = rem - b * FFP;
        float v = 0.f;
        if (f < 2)        v = inputs[(size_t)b * (NN*2) + n*2 + f];
        else if (f < FF)  v = hx[(size_t)b * (NN*UNITS) + n*UNITS + (f-2)];
        g_X0h[i] = __float2half_rn(v);
    }
}

// ---------------- fma helper: acc[8] += w * unpack(uint4 of 8 halves) ---------
__device__ __forceinline__ void hfma8(float* acc, uint4 v, float w) {
    const __half2* h = (const __half2*)&v;
    #pragma unroll
    for (int p = 0; p < 4; p++) {
        float2 f = __half22float2(h[p]);
        acc[2*p]   += w * f.x;
        acc[2*p+1] += w * f.y;
    }
}

// ---------------- spmm pass 1: x1 = S @ x0 -------------------------------------
__global__ void spmm_h() {
    int s = blockIdx.y;
    const int*   ptr = s ? g_ptr1  : g_ptr0;
    const int*   ci  = s ? g_cidx1 : g_cidx0;
    const float* cv  = s ? g_cval1 : g_cval0;
    __half*      y   = s ? g_X1bh  : g_X1ah;
    const uint4* X   = (const uint4*)g_X0h;
    int n = blockIdx.x;
    int beg = ptr[n], end = ptr[n+1];
    for (int i = threadIdx.x; i < VECP; i += blockDim.x) {
        float acc[8];
        #pragma unroll
        for (int j = 0; j < 8; j++) acc[j] = 0.f;
        for (int e = beg; e < end; e++)
            hfma8(acc, X[(size_t)ci[e] * VECP + i], cv[e]);
        uint4 o;
        __half2* oh = (__half2*)&o;
        #pragma unroll
        for (int p = 0; p < 4; p++)
            oh[p] = __floats2half2_rn(acc[2*p], acc[2*p+1]);
        ((uint4*)y)[(size_t)n * VECP + i] = o;
    }
}

// ---------------- spmm pass 2: x2 = 2 S @ x1 - x0 ------------------------------
__global__ void spmm2_h() {
    int s = blockIdx.y;
    const int*   ptr = s ? g_ptr1  : g_ptr0;
    const int*   ci  = s ? g_cidx1 : g_cidx0;
    const float* cv  = s ? g_cval1 : g_cval0;
    const uint4* X1  = (const uint4*)(s ? g_X1bh : g_X1ah);
    __half*      y   = s ? g_X2bh  : g_X2ah;
    const uint4* X0  = (const uint4*)g_X0h;
    int n = blockIdx.x;
    int beg = ptr[n], end = ptr[n+1];
    for (int i = threadIdx.x; i < VECP; i += blockDim.x) {
        float acc[8];
        uint4 v0 = X0[(size_t)n * VECP + i];
        {
            const __half2* h = (const __half2*)&v0;
            #pragma unroll
            for (int p = 0; p < 4; p++) {
                float2 f = __half22float2(h[p]);
                acc[2*p] = -f.x; acc[2*p+1] = -f.y;
            }
        }
        for (int e = beg; e < end; e++)
            hfma8(acc, X1[(size_t)ci[e] * VECP + i], 2.f * cv[e]);
        uint4 o;
        __half2* oh = (__half2*)&o;
        #pragma unroll
        for (int p = 0; p < 4; p++)
            oh[p] = __floats2half2_rn(acc[2*p], acc[2*p+1]);
        ((uint4*)y)[(size_t)n * VECP + i] = o;
    }
}

// ---------------- fp16 mma helper ----------------------------------------------
__device__ __forceinline__ void mma_f16(float* d, const unsigned* a, const unsigned* b) {
    asm volatile(
        "mma.sync.aligned.m16n8k16.row.col.f32.f16.f16.f32 "
        "{%0,%1,%2,%3}, {%4,%5,%6,%7}, {%8,%9}, {%0,%1,%2,%3};\n"
        : "+f"(d[0]), "+f"(d[1]), "+f"(d[2]), "+f"(d[3])
        : "r"(a[0]), "r"(a[1]), "r"(a[2]), "r"(a[3]), "r"(b[0]), "r"(b[1]));
}

// ---------------- gather one 64-row A tile: pure coalesced copy ----------------
// planar layout: k' = m*FFP + f; per task 5 LDG.128 + 5 STS.128, no math.
__device__ __forceinline__ void gather_tile(int t, __half* As, int tid) {
    const uint4* P0 = (const uint4*)g_X0h;
    const uint4* P1 = (const uint4*)g_X1ah;
    const uint4* P2 = (const uint4*)g_X2ah;
    const uint4* P3 = (const uint4*)g_X1bh;
    const uint4* P4 = (const uint4*)g_X2bh;
    for (int task = tid; task < 2 * VECP; task += 512) {
        int ln = (task >= VECP) ? 1 : 0;
        int i  = task - ln * VECP;            // i = b*9 + oct
        int n  = t * 2 + ln;
        int b  = i / OCT, oct = i - b * OCT;
        size_t src = (size_t)n * VECP + i;
        uint4* dstrow = (uint4*)As + (ln * 32 + b) * (ASTR / 8);
        dstrow[0*OCT + oct] = P0[src];
        dstrow[1*OCT + oct] = P1[src];
        dstrow[2*OCT + oct] = P2[src];
        dstrow[3*OCT + oct] = P3[src];
        dstrow[4*OCT + oct] = P4[src];
    }
}

// =====================================================================
// Persistent fused gconv: W staged once (planar-permuted), loop 64-row
// tiles with double-buffered A (copy t+1 overlaps MMA on t).
// =====================================================================
template<int NCOLS, int GCONV>
__global__ __launch_bounds__(512) void fused_gconv_p(
        const float* __restrict__ W, const float* __restrict__ bias,
        const float* __restrict__ hx, float* __restrict__ out) {
    extern __shared__ __half smem[];
    __half* Ws = smem;                         // [NCOLS][ASTR]
    __half* A0 = smem + NCOLS * ASTR;          // [64][ASTR]
    __half* A1 = A0 + MROWS * ASTR;

    int tid = threadIdx.x;

    // stage W once: [col][k'], planar permutation k' = m*FFP + f
    for (int idx = tid; idx < KPADP * NCOLS; idx += 512) {
        int k = idx / NCOLS, c = idx - k * NCOLS;
        float v = 0.f;
        if (k < KDIMP) {
            int m = k / FFP, f = k - m * FFP;
            if (f < FF) v = W[(f * MM + m) * NCOLS + c];
        }
        Ws[c * ASTR + k] = __float2half_rn(v);
    }
    // zero A k-pad [360,368) of both buffers once (copy never touches it)
    {
        uint4 z = make_uint4(0,0,0,0);
        for (int r = tid; r < 2 * MROWS; r += 512) {
            __half* buf = (r < MROWS) ? A0 : A1;
            ((uint4*)&buf[(r & (MROWS-1)) * ASTR])[KDIMP/8] = z;   // uint4 idx 45
        }
    }

    int lane = tid & 31, w = tid >> 5;
    int warpM = w & 3, warpN = w >> 2;        // 4 x 4 warps: 16 rows x NCOLS/4 cols
    int g = lane >> 2, tq = lane & 3;
    constexpr int NJ = NCOLS / 32;            // n-tiles of 8 per warp (4 or 2)

    int it = 0;
    for (int t = blockIdx.x; t < NTILES; t += PGRID, ++it) {
        __half* cur = (it & 1) ? A1 : A0;
        __half* nxt = (it & 1) ? A0 : A1;
        if (it == 0) {
            gather_tile(t, cur, tid);
            __syncthreads();
        }
        int tn = t + PGRID;
        if (tn < NTILES) gather_tile(tn, nxt, tid);

        // ---- MMA on cur ----
        float acc[NJ][4];
        #pragma unroll
        for (int j = 0; j < NJ; j++)
            #pragma unroll
            for (int q = 0; q < 4; q++) acc[j][q] = 0.f;

        int rA = (warpM * 16 + g) * ASTR;
        #pragma unroll
        for (int kt = 0; kt < KPADP / 16; kt++) {
            int kb = kt * 16;
            unsigned a[4];
            a[0] = *(const unsigned*)&cur[rA + kb + 2*tq];
            a[1] = *(const unsigned*)&cur[rA + 8 * ASTR + kb + 2*tq];
            a[2] = *(const unsigned*)&cur[rA + kb + 2*tq + 8];
            a[3] = *(const unsigned*)&cur[rA + 8 * ASTR + kb + 2*tq + 8];
            #pragma unroll
            for (int j = 0; j < NJ; j++) {
                unsigned b[2];
                int c = warpN * (NCOLS/4) + j * 8 + g;
                b[0] = *(const unsigned*)&Ws[c * ASTR + kb + 2*tq];
                b[1] = *(const unsigned*)&Ws[c * ASTR + kb + 2*tq + 8];
                mma_f16(acc[j], a, b);
            }
        }

        // ---- epilogue for tile t ----
        #pragma unroll
        for (int j = 0; j < NJ; j++) {
            int col0 = warpN * (NCOLS/4) + j * 8 + 2 * tq;
            #pragma unroll
            for (int half = 0; half < 2; half++) {
                int row = t * MROWS + warpM * 16 + g + half * 8;
                int n = row >> 5, bb = row & 31;
                #pragma unroll
                for (int q = 0; q < 2; q++) {
                    int col = col0 + q;
                    float v = acc[j][half * 2 + q] + bias[col];
                    if (GCONV == 1) {
                        v = 1.f / (1.f + __expf(-v));
                        if (col < UNITS) {
                            float h = hx[(size_t)bb * (NN*UNITS) + n*UNITS + col];
                            g_X0h[(size_t)n * NBFP + bb*FFP + 2 + col] = __float2half_rn(v * h);
                        } else {
                            g_U[(size_t)row * UNITS + (col - UNITS)] = v;
                        }
                    } else {
                        float c = tanhf(v);
                        float u = g_U[(size_t)row * UNITS + col];
                        float h = hx[(size_t)bb * (NN*UNITS) + n*UNITS + col];
                        out[(size_t)bb * (NN*UNITS) + n*UNITS + col] = u * h + (1.f - u) * c;
                    }
                }
            }
        }
        __syncthreads();
    }
}

// ---------------- launch --------------------------------------------------------
extern "C" void kernel_launch(void* const* d_in, const int* in_sizes, int n_in,
                              void* d_out, int out_size) {
    const float* inputs = (const float*)d_in[0];
    const float* hx     = (const float*)d_in[1];
    const float* W_ru   = (const float*)d_in[2];
    const float* b_ru   = (const float*)d_in[3];
    const float* W_c    = (const float*)d_in[4];
    const float* b_c    = (const float*)d_in[5];
    const int*   s0r    = (const int*)d_in[6];
    const int*   s0c    = (const int*)d_in[7];
    const float* s0v    = (const float*)d_in[8];
    const int*   s1r    = (const int*)d_in[9];
    const int*   s1c    = (const int*)d_in[10];
    const float* s1v    = (const float*)d_in[11];
    int E = in_sizes[6];
    float* out = (float*)d_out;

    const int smem1 = (128 + 2 * MROWS) * ASTR * 2;   // 192512 B
    const int smem2 = (64  + 2 * MROWS) * ASTR * 2;   // 144384 B
    cudaFuncSetAttribute(fused_gconv_p<128,1>, cudaFuncAttributeMaxDynamicSharedMemorySize, smem1);
    cudaFuncSetAttribute(fused_gconv_p<64,2>,  cudaFuncAttributeMaxDynamicSharedMemorySize, smem2);

    // 0-2: CSR build + x0
    csr_count<<<(E + 255)/256, 256>>>(s0r, s1r, E);
    csr_scan<<<2, 1024>>>();
    long long tasks = 2LL*E + (long long)NN*NBFP;
    scatter_build<<<(unsigned)((tasks + 255)/256), 256>>>(s0r, s0c, s0v, s1r, s1c, s1v, E,
                                                          inputs, hx);

    dim3 spmmGrid(NN, 2);

    // gconv #1 (gates)
    spmm_h <<<spmmGrid, 256>>>();     // 3
    spmm2_h<<<spmmGrid, 256>>>();     // 4
    fused_gconv_p<128,1><<<PGRID, 512, smem1>>>(W_ru, b_ru, hx, out);   // 5 (profiled)

    // gconv #2 (candidate) + final combine
    spmm_h <<<spmmGrid, 256>>>();     // 6
    spmm2_h<<<spmmGrid, 256>>>();     // 7
    fused_gconv_p<64,2><<<PGRID, 512, smem2>>>(W_c, b_c, hx, out);      // 8
}

// round 14
// speedup vs baseline: 3.6945x; 1.1999x over previous
#include <cuda_runtime.h>
#include <cuda_fp16.h>
#include <math.h>

// Problem constants (fixed by the dataset)
#define NN    8000
#define BB    32
#define FF    66            // input_dim(2) + units(64)
#define FFP   72            // padded F (octet-aligned; pads are zero)
#define NBFP  (BB*FFP)      // 2304
#define MM    5             // num diffusion matrices = 2*K+1
#define KDIMP (MM*FFP)      // 360 (planar K: k' = m*72 + f)
#define KPADP 368           // 23 * 16
#define ASTR  376           // smem k-stride in halves (47 uint4; conflict-free frags)
#define UNITS 64
#define EMAX  64000
#define VECP  (NBFP/8)      // 288 uint4 per node row
#define OCT   (FFP/8)       // 9 octets per batch lane
#define MROWS 64            // GEMM rows per tile = 2 nodes
#define NTILES (NN*BB/MROWS)   // 4000
#define PGRID 152           // persistent blocks

// ---------------- scratch (static device globals) -----------------------------
__device__ __align__(16) __half g_X0h [NN*NBFP];   // (N, B, Fp) fp16
__device__ __align__(16) __half g_X1ah[NN*NBFP];   // S0 @ x0
__device__ __align__(16) __half g_X1bh[NN*NBFP];   // S1 @ x0
__device__ __align__(16) __half g_X2ah[NN*NBFP];   // 2 S0 x1a - x0
__device__ __align__(16) __half g_X2bh[NN*NBFP];   // 2 S1 x1b - x0
__device__ float g_U  [(size_t)NN*BB*UNITS];       // update gate u (fp32)
__device__ int   g_ptr0[NN+1], g_ptr1[NN+1];
__device__ int   g_cidx0[EMAX], g_cidx1[EMAX];
__device__ float g_cval0[EMAX], g_cval1[EMAX];
__device__ int   g_cnt[2*NN];   // zero at start of each call (self-cleaning)
__device__ int   g_cur[2*NN];

// ---------------- CSR build (self-cleaning) ------------------------------------
__global__ void csr_count(const int* __restrict__ r0, const int* __restrict__ r1, int E) {
    int e = blockIdx.x * blockDim.x + threadIdx.x;
    if (e < 2*NN) g_cur[e] = 0;
    if (e < E) {
        atomicAdd(&g_cnt[r0[e]], 1);
        atomicAdd(&g_cnt[NN + r1[e]], 1);
    }
}

__global__ void csr_scan() {
    int s = blockIdx.x;
    int* cnt = g_cnt + s * NN;
    int* ptr = s ? g_ptr1 : g_ptr0;
    __shared__ int sm[1024];
    __shared__ int carry;
    if (threadIdx.x == 0) carry = 0;
    __syncthreads();
    for (int base = 0; base < NN; base += 1024) {
        int i = base + threadIdx.x;
        int v = (i < NN) ? cnt[i] : 0;
        if (i < NN) cnt[i] = 0;          // self-clean for next call
        sm[threadIdx.x] = v;
        __syncthreads();
        int c0 = carry;
        for (int off = 1; off < 1024; off <<= 1) {
            int t = (threadIdx.x >= (unsigned)off) ? sm[threadIdx.x - off] : 0;
            __syncthreads();
            sm[threadIdx.x] += t;
            __syncthreads();
        }
        if (i < NN) ptr[i] = c0 + sm[threadIdx.x] - v;
        __syncthreads();
        if (threadIdx.x == 1023) carry = c0 + sm[1023];
        __syncthreads();
    }
    if (threadIdx.x == 0) ptr[NN] = carry;
}

// scatter (both supports) fused with build_x0 (padded fp16 layout)
__global__ void scatter_build(const int* __restrict__ r0c, const int* __restrict__ c0c,
                              const float* __restrict__ v0c,
                              const int* __restrict__ r1c, const int* __restrict__ c1c,
                              const float* __restrict__ v1c, int E,
                              const float* __restrict__ inputs, const float* __restrict__ hx) {
    long long idx = (long long)blockIdx.x * blockDim.x + threadIdx.x;
    if (idx < 2*E) {
        int s = idx >= E;
        int e = (int)(s ? idx - E : idx);
        const int*   r = s ? r1c : r0c;
        const int*   c = s ? c1c : c0c;
        const float* v = s ? v1c : v0c;
        int row = r[e];
        int p = (s ? g_ptr1 : g_ptr0)[row] + atomicAdd(&g_cur[s*NN + row], 1);
        (s ? g_cidx1 : g_cidx0)[p] = c[e];
        (s ? g_cval1 : g_cval0)[p] = v[e];
        return;
    }
    long long i = idx - 2*E;
    if (i < (long long)NN * NBFP) {
        int n = (int)(i / NBFP);
        int rem = (int)(i - (long long)n * NBFP);
        int b = rem / FFP;
        int f = rem - b * FFP;
        float v = 0.f;
        if (f < 2)        v = inputs[(size_t)b * (NN*2) + n*2 + f];
        else if (f < FF)  v = hx[(size_t)b * (NN*UNITS) + n*UNITS + (f-2)];
        g_X0h[i] = __float2half_rn(v);
    }
}

// ---------------- fma helper: acc[8] += w * unpack(uint4 of 8 halves) ---------
__device__ __forceinline__ void hfma8(float* acc, uint4 v, float w) {
    const __half2* h = (const __half2*)&v;
    #pragma unroll
    for (int p = 0; p < 4; p++) {
        float2 f = __half22float2(h[p]);
        acc[2*p]   += w * f.x;
        acc[2*p+1] += w * f.y;
    }
}

// ---------------- spmm pass 1: x1 = S @ x0 (288 threads = exactly VECP) -------
__global__ __launch_bounds__(VECP) void spmm_h() {
    int s = blockIdx.y;
    const int*   ptr = s ? g_ptr1  : g_ptr0;
    const int*   ci  = s ? g_cidx1 : g_cidx0;
    const float* cv  = s ? g_cval1 : g_cval0;
    __half*      y   = s ? g_X1bh  : g_X1ah;
    const uint4* X   = (const uint4*)g_X0h;
    int n = blockIdx.x;
    int beg = ptr[n], end = ptr[n+1];
    int i = threadIdx.x;
    float acc[8];
    #pragma unroll
    for (int j = 0; j < 8; j++) acc[j] = 0.f;
    for (int e = beg; e < end; e++)
        hfma8(acc, X[(size_t)ci[e] * VECP + i], cv[e]);
    uint4 o;
    __half2* oh = (__half2*)&o;
    #pragma unroll
    for (int p = 0; p < 4; p++)
        oh[p] = __floats2half2_rn(acc[2*p], acc[2*p+1]);
    ((uint4*)y)[(size_t)n * VECP + i] = o;
}

// ---------------- spmm pass 2: x2 = 2 S @ x1 - x0 ------------------------------
__global__ __launch_bounds__(VECP) void spmm2_h() {
    int s = blockIdx.y;
    const int*   ptr = s ? g_ptr1  : g_ptr0;
    const int*   ci  = s ? g_cidx1 : g_cidx0;
    const float* cv  = s ? g_cval1 : g_cval0;
    const uint4* X1  = (const uint4*)(s ? g_X1bh : g_X1ah);
    __half*      y   = s ? g_X2bh  : g_X2ah;
    const uint4* X0  = (const uint4*)g_X0h;
    int n = blockIdx.x;
    int beg = ptr[n], end = ptr[n+1];
    int i = threadIdx.x;
    float acc[8];
    uint4 v0 = X0[(size_t)n * VECP + i];
    {
        const __half2* h = (const __half2*)&v0;
        #pragma unroll
        for (int p = 0; p < 4; p++) {
            float2 f = __half22float2(h[p]);
            acc[2*p] = -f.x; acc[2*p+1] = -f.y;
        }
    }
    for (int e = beg; e < end; e++)
        hfma8(acc, X1[(size_t)ci[e] * VECP + i], 2.f * cv[e]);
    uint4 o;
    __half2* oh = (__half2*)&o;
    #pragma unroll
    for (int p = 0; p < 4; p++)
        oh[p] = __floats2half2_rn(acc[2*p], acc[2*p+1]);
    ((uint4*)y)[(size_t)n * VECP + i] = o;
}

// ---------------- mma / ldmatrix / cp.async helpers ----------------------------
__device__ __forceinline__ void mma_f16(float* d, const unsigned* a, const unsigned* b) {
    asm volatile(
        "mma.sync.aligned.m16n8k16.row.col.f32.f16.f16.f32 "
        "{%0,%1,%2,%3}, {%4,%5,%6,%7}, {%8,%9}, {%0,%1,%2,%3};\n"
        : "+f"(d[0]), "+f"(d[1]), "+f"(d[2]), "+f"(d[3])
        : "r"(a[0]), "r"(a[1]), "r"(a[2]), "r"(a[3]), "r"(b[0]), "r"(b[1]));
}

__device__ __forceinline__ void ldsm_x4(unsigned* r, unsigned addr) {
    asm volatile("ldmatrix.sync.aligned.m8n8.x4.shared.b16 {%0,%1,%2,%3}, [%4];"
        : "=r"(r[0]), "=r"(r[1]), "=r"(r[2]), "=r"(r[3]) : "r"(addr));
}

__device__ __forceinline__ void cpasync16(unsigned saddr, const void* gptr) {
    asm volatile("cp.async.cg.shared.global [%0], [%1], 16;" :: "r"(saddr), "l"(gptr));
}
__device__ __forceinline__ void cpasync_commit() {
    asm volatile("cp.async.commit_group;");
}
__device__ __forceinline__ void cpasync_wait0() {
    asm volatile("cp.async.wait_group 0;");
}

// ---------------- gather one 64-row A tile via cp.async (non-blocking) --------
__device__ __forceinline__ void gather_tile_async(int t, unsigned As_addr, int tid) {
    const uint4* P0 = (const uint4*)g_X0h;
    const uint4* P1 = (const uint4*)g_X1ah;
    const uint4* P2 = (const uint4*)g_X2ah;
    const uint4* P3 = (const uint4*)g_X1bh;
    const uint4* P4 = (const uint4*)g_X2bh;
    #pragma unroll 2
    for (int task = tid; task < 2 * VECP; task += 512) {
        int ln = (task >= VECP) ? 1 : 0;
        int i  = task - ln * VECP;            // i = b*9 + oct
        int n  = t * 2 + ln;
        int b  = i / OCT, oct = i - b * OCT;
        size_t src = (size_t)n * VECP + i;
        unsigned drow = As_addr + (unsigned)((ln * 32 + b) * ASTR * 2) + oct * 16u;
        cpasync16(drow + 0*OCT*16u, &P0[src]);
        cpasync16(drow + 1*OCT*16u, &P1[src]);
        cpasync16(drow + 2*OCT*16u, &P2[src]);
        cpasync16(drow + 3*OCT*16u, &P3[src]);
        cpasync16(drow + 4*OCT*16u, &P4[src]);
    }
}

// =====================================================================
// Persistent fused gconv: W staged once (planar-permuted); loop 64-row
// tiles, cp.async double-buffered A (copy t+1 truly overlaps MMA on t);
// ldmatrix fragment loads.
// =====================================================================
template<int NCOLS, int GCONV>
__global__ __launch_bounds__(512) void fused_gconv_p(
        const float* __restrict__ W, const float* __restrict__ bias,
        const float* __restrict__ hx, float* __restrict__ out) {
    extern __shared__ __half smem[];
    __half* Ws = smem;                         // [NCOLS][ASTR]
    __half* A0 = smem + NCOLS * ASTR;          // [64][ASTR]
    __half* A1 = A0 + MROWS * ASTR;

    int tid = threadIdx.x;
    unsigned Ws_addr = (unsigned)__cvta_generic_to_shared(Ws);
    unsigned A0_addr = (unsigned)__cvta_generic_to_shared(A0);
    unsigned A1_addr = (unsigned)__cvta_generic_to_shared(A1);

    // stage W once: [col][k'], planar permutation k' = m*FFP + f
    for (int idx = tid; idx < KPADP * NCOLS; idx += 512) {
        int k = idx / NCOLS, c = idx - k * NCOLS;
        float v = 0.f;
        if (k < KDIMP) {
            int m = k / FFP, f = k - m * FFP;
            if (f < FF) v = W[(f * MM + m) * NCOLS + c];
        }
        Ws[c * ASTR + k] = __float2half_rn(v);
    }
    // zero A k-pad [360,368) of both buffers once (copy never touches it)
    {
        uint4 z = make_uint4(0,0,0,0);
        for (int r = tid; r < 2 * MROWS; r += 512) {
            __half* buf = (r < MROWS) ? A0 : A1;
            ((uint4*)&buf[(r & (MROWS-1)) * ASTR])[KDIMP/8] = z;
        }
    }

    int lane = tid & 31, w = tid >> 5;
    int warpM = w & 3, warpN = w >> 2;        // 4 x 4 warps: 16 rows x NCOLS/4 cols
    int g = lane >> 2, tq = lane & 3;
    constexpr int NJ = NCOLS / 32;            // n-tiles of 8 per warp (4 or 2)

    // ldmatrix lane addressing (byte offsets within a buffer)
    int lt = lane >> 3, lr = lane & 7;                    // tile idx, row within tile
    // A: tiles [r0-7,k0-7],[r8-15,k0-7],[r0-7,k8-15],[r8-15,k8-15]
    unsigned aOff = (unsigned)(((warpM * 16 + (lt & 1) * 8 + lr) * ASTR + (lt >> 1) * 8) * 2);
    // B: per j-pair p: tiles [n0-7,k0-7],[n0-7,k8-15],[n8-15,k0-7],[n8-15,k8-15]
    unsigned bOff[NJ/2];
    #pragma unroll
    for (int p = 0; p < NJ/2; p++) {
        int c = warpN * (NCOLS/4) + p * 16 + (lt >> 1) * 8 + lr;
        bOff[p] = Ws_addr + (unsigned)((c * ASTR + (lt & 1) * 8) * 2);
    }

    int it = 0;
    for (int t = blockIdx.x; t < NTILES; t += PGRID, ++it) {
        unsigned curA = (it & 1) ? A1_addr : A0_addr;
        unsigned nxtA = (it & 1) ? A0_addr : A1_addr;
        if (it == 0) {
            gather_tile_async(t, curA, tid);
            cpasync_commit();
            cpasync_wait0();
            __syncthreads();
        }
        int tn = t + PGRID;
        if (tn < NTILES) gather_tile_async(tn, nxtA, tid);
        cpasync_commit();

        // ---- MMA on cur (ldmatrix fragments) ----
        float acc[NJ][4];
        #pragma unroll
        for (int j = 0; j < NJ; j++)
            #pragma unroll
            for (int q = 0; q < 4; q++) acc[j][q] = 0.f;

        #pragma unroll
        for (int kt = 0; kt < KPADP / 16; kt++) {
            unsigned kbB = (unsigned)(kt * 16 * 2);     // byte offset along k
            unsigned a[4];
            ldsm_x4(a, curA + aOff + kbB);
            #pragma unroll
            for (int p = 0; p < NJ/2; p++) {
                unsigned b4[4];                          // b[j][0..1], b[j+1][0..1]
                ldsm_x4(b4, bOff[p] + kbB);
                mma_f16(acc[2*p],     a, b4);
                mma_f16(acc[2*p + 1], a, b4 + 2);
            }
        }

        // ---- epilogue for tile t (uses only regs + gmem) ----
        #pragma unroll
        for (int j = 0; j < NJ; j++) {
            int col0 = warpN * (NCOLS/4) + j * 8 + 2 * tq;
            #pragma unroll
            for (int half = 0; half < 2; half++) {
                int row = t * MROWS + warpM * 16 + g + half * 8;
                int n = row >> 5, bb = row & 31;
                #pragma unroll
                for (int q = 0; q < 2; q++) {
                    int col = col0 + q;
                    float v = acc[j][half * 2 + q] + bias[col];
                    if (GCONV == 1) {
                        v = 1.f / (1.f + __expf(-v));
                        if (col < UNITS) {
                            float h = hx[(size_t)bb * (NN*UNITS) + n*UNITS + col];
                            g_X0h[(size_t)n * NBFP + bb*FFP + 2 + col] = __float2half_rn(v * h);
                        } else {
                            g_U[(size_t)row * UNITS + (col - UNITS)] = v;
                        }
                    } else {
                        float c = tanhf(v);
                        float u = g_U[(size_t)row * UNITS + col];
                        float h = hx[(size_t)bb * (NN*UNITS) + n*UNITS + col];
                        out[(size_t)bb * (NN*UNITS) + n*UNITS + col] = u * h + (1.f - u) * c;
                    }
                }
            }
        }
        cpasync_wait0();
        __syncthreads();
    }
}

// ---------------- launch --------------------------------------------------------
extern "C" void kernel_launch(void* const* d_in, const int* in_sizes, int n_in,
                              void* d_out, int out_size) {
    const float* inputs = (const float*)d_in[0];
    const float* hx     = (const float*)d_in[1];
    const float* W_ru   = (const float*)d_in[2];
    const float* b_ru   = (const float*)d_in[3];
    const float* W_c    = (const float*)d_in[4];
    const float* b_c    = (const float*)d_in[5];
    const int*   s0r    = (const int*)d_in[6];
    const int*   s0c    = (const int*)d_in[7];
    const float* s0v    = (const float*)d_in[8];
    const int*   s1r    = (const int*)d_in[9];
    const int*   s1c    = (const int*)d_in[10];
    const float* s1v    = (const float*)d_in[11];
    int E = in_sizes[6];
    float* out = (float*)d_out;

    const int smem1 = (128 + 2 * MROWS) * ASTR * 2;   // 192512 B
    const int smem2 = (64  + 2 * MROWS) * ASTR * 2;   // 144384 B
    cudaFuncSetAttribute(fused_gconv_p<128,1>, cudaFuncAttributeMaxDynamicSharedMemorySize, smem1);
    cudaFuncSetAttribute(fused_gconv_p<64,2>,  cudaFuncAttributeMaxDynamicSharedMemorySize, smem2);

    // 0-2: CSR build + x0
    csr_count<<<(E + 255)/256, 256>>>(s0r, s1r, E);
    csr_scan<<<2, 1024>>>();
    long long tasks = 2LL*E + (long long)NN*NBFP;
    scatter_build<<<(unsigned)((tasks + 255)/256), 256>>>(s0r, s0c, s0v, s1r, s1c, s1v, E,
                                                          inputs, hx);

    dim3 spmmGrid(NN, 2);

    // gconv #1 (gates)
    spmm_h <<<spmmGrid, VECP>>>();    // 3
    spmm2_h<<<spmmGrid, VECP>>>();    // 4
    fused_gconv_p<128,1><<<PGRID, 512, smem1>>>(W_ru, b_ru, hx, out);   // 5

    // gconv #2 (candidate) + final combine
    spmm_h <<<spmmGrid, VECP>>>();    // 6
    spmm2_h<<<spmmGrid, VECP>>>();    // 7
    fused_gconv_p<64,2><<<PGRID, 512, smem2>>>(W_c, b_c, hx, out);      // 8
}

// round 16
// speedup vs baseline: 4.0186x; 1.0877x over previous
#include <cuda_runtime.h>
#include <cuda_fp16.h>
#include <cuda.h>
#include <math.h>

// Problem constants (fixed by the dataset)
#define NN    8000
#define BB    32
#define FF    66            // input_dim(2) + units(64)
#define FFP   72            // padded F (octet-aligned; pads are zero)
#define NBFP  (BB*FFP)      // 2304
#define MM    5             // num diffusion matrices = 2*K+1
#define KDIMP (MM*FFP)      // 360 (planar K: k' = m*72 + f)
#define WSTR  376           // Ws smem k-stride in halves (conflict-free frags)
#define UNITS 64
#define EMAX  64000
#define VECP  (NBFP/8)      // 288 uint4 per node row
#define MROWS 64            // GEMM rows per tile = 2 nodes
#define NTILES (NN*BB/MROWS)   // 4000
#define PGRID 152           // persistent blocks
#define PLANEB 9216         // bytes per A smem plane: 64 rows x 144 B (mult of 128)
#define ABUFB  (5*PLANEB)   // 46080 B per A buffer (mult of 128)

// ---------------- scratch (static device globals) -----------------------------
__device__ __align__(16) __half g_X0h [NN*NBFP];   // (N*B, 72) fp16, row=(n*32+b)
__device__ __align__(16) __half g_X1ah[NN*NBFP];   // S0 @ x0
__device__ __align__(16) __half g_X1bh[NN*NBFP];   // S1 @ x0
__device__ __align__(16) __half g_X2ah[NN*NBFP];   // 2 S0 x1a - x0
__device__ __align__(16) __half g_X2bh[NN*NBFP];   // 2 S1 x1b - x0
__device__ float g_U  [(size_t)NN*BB*UNITS];       // update gate u (fp32)
__device__ int   g_ptr0[NN+1], g_ptr1[NN+1];
__device__ int   g_cidx0[EMAX], g_cidx1[EMAX];
__device__ float g_cval0[EMAX], g_cval1[EMAX];
__device__ int   g_cnt[2*NN];   // zero at start of each call (self-cleaning)
__device__ int   g_cur[2*NN];

// ---------------- CSR build (self-cleaning) ------------------------------------
__global__ void csr_count(const int* __restrict__ r0, const int* __restrict__ r1, int E) {
    int e = blockIdx.x * blockDim.x + threadIdx.x;
    if (e < 2*NN) g_cur[e] = 0;
    if (e < E) {
        atomicAdd(&g_cnt[r0[e]], 1);
        atomicAdd(&g_cnt[NN + r1[e]], 1);
    }
}

__global__ void csr_scan() {
    int s = blockIdx.x;
    int* cnt = g_cnt + s * NN;
    int* ptr = s ? g_ptr1 : g_ptr0;
    __shared__ int sm[1024];
    __shared__ int carry;
    if (threadIdx.x == 0) carry = 0;
    __syncthreads();
    for (int base = 0; base < NN; base += 1024) {
        int i = base + threadIdx.x;
        int v = (i < NN) ? cnt[i] : 0;
        if (i < NN) cnt[i] = 0;          // self-clean for next call
        sm[threadIdx.x] = v;
        __syncthreads();
        int c0 = carry;
        for (int off = 1; off < 1024; off <<= 1) {
            int t = (threadIdx.x >= (unsigned)off) ? sm[threadIdx.x - off] : 0;
            __syncthreads();
            sm[threadIdx.x] += t;
            __syncthreads();
        }
        if (i < NN) ptr[i] = c0 + sm[threadIdx.x] - v;
        __syncthreads();
        if (threadIdx.x == 1023) carry = c0 + sm[1023];
        __syncthreads();
    }
    if (threadIdx.x == 0) ptr[NN] = carry;
}

// scatter (both supports) fused with build_x0 (padded fp16 layout)
__global__ void scatter_build(const int* __restrict__ r0c, const int* __restrict__ c0c,
                              const float* __restrict__ v0c,
                              const int* __restrict__ r1c, const int* __restrict__ c1c,
                              const float* __restrict__ v1c, int E,
                              const float* __restrict__ inputs, const float* __restrict__ hx) {
    long long idx = (long long)blockIdx.x * blockDim.x + threadIdx.x;
    if (idx < 2*E) {
        int s = idx >= E;
        int e = (int)(s ? idx - E : idx);
        const int*   r = s ? r1c : r0c;
        const int*   c = s ? c1c : c0c;
        const float* v = s ? v1c : v0c;
        int row = r[e];
        int p = (s ? g_ptr1 : g_ptr0)[row] + atomicAdd(&g_cur[s*NN + row], 1);
        (s ? g_cidx1 : g_cidx0)[p] = c[e];
        (s ? g_cval1 : g_cval0)[p] = v[e];
        return;
    }
    long long i = idx - 2*E;
    if (i < (long long)NN * NBFP) {
        int n = (int)(i / NBFP);
        int rem = (int)(i - (long long)n * NBFP);
        int b = rem / FFP;
        int f = rem - b * FFP;
        float v = 0.f;
        if (f < 2)        v = inputs[(size_t)b * (NN*2) + n*2 + f];
        else if (f < FF)  v = hx[(size_t)b * (NN*UNITS) + n*UNITS + (f-2)];
        g_X0h[i] = __float2half_rn(v);
    }
}

// ---------------- fma helper: acc[8] += w * unpack(uint4 of 8 halves) ---------
__device__ __forceinline__ void hfma8(float* acc, uint4 v, float w) {
    const __half2* h = (const __half2*)&v;
    #pragma unroll
    for (int p = 0; p < 4; p++) {
        float2 f = __half22float2(h[p]);
        acc[2*p]   += w * f.x;
        acc[2*p+1] += w * f.y;
    }
}

// ---------------- spmm pass 1: x1 = S @ x0 (288 threads = exactly VECP) -------
__global__ __launch_bounds__(VECP) void spmm_h() {
    int s = blockIdx.y;
    const int*   ptr = s ? g_ptr1  : g_ptr0;
    const int*   ci  = s ? g_cidx1 : g_cidx0;
    const float* cv  = s ? g_cval1 : g_cval0;
    __half*      y   = s ? g_X1bh  : g_X1ah;
    const uint4* X   = (const uint4*)g_X0h;
    int n = blockIdx.x;
    int beg = ptr[n], end = ptr[n+1];
    int i = threadIdx.x;
    float acc[8];
    #pragma unroll
    for (int j = 0; j < 8; j++) acc[j] = 0.f;
    for (int e = beg; e < end; e++)
        hfma8(acc, X[(size_t)ci[e] * VECP + i], cv[e]);
    uint4 o;
    __half2* oh = (__half2*)&o;
    #pragma unroll
    for (int p = 0; p < 4; p++)
        oh[p] = __floats2half2_rn(acc[2*p], acc[2*p+1]);
    ((uint4*)y)[(size_t)n * VECP + i] = o;
}

// ---------------- spmm pass 2: x2 = 2 S @ x1 - x0 ------------------------------
__global__ __launch_bounds__(VECP) void spmm2_h() {
    int s = blockIdx.y;
    const int*   ptr = s ? g_ptr1  : g_ptr0;
    const int*   ci  = s ? g_cidx1 : g_cidx0;
    const float* cv  = s ? g_cval1 : g_cval0;
    const uint4* X1  = (const uint4*)(s ? g_X1bh : g_X1ah);
    __half*      y   = s ? g_X2bh  : g_X2ah;
    const uint4* X0  = (const uint4*)g_X0h;
    int n = blockIdx.x;
    int beg = ptr[n], end = ptr[n+1];
    int i = threadIdx.x;
    float acc[8];
    uint4 v0 = X0[(size_t)n * VECP + i];
    {
        const __half2* h = (const __half2*)&v0;
        #pragma unroll
        for (int p = 0; p < 4; p++) {
            float2 f = __half22float2(h[p]);
            acc[2*p] = -f.x; acc[2*p+1] = -f.y;
        }
    }
    for (int e = beg; e < end; e++)
        hfma8(acc, X1[(size_t)ci[e] * VECP + i], 2.f * cv[e]);
    uint4 o;
    __half2* oh = (__half2*)&o;
    #pragma unroll
    for (int p = 0; p < 4; p++)
        oh[p] = __floats2half2_rn(acc[2*p], acc[2*p+1]);
    ((uint4*)y)[(size_t)n * VECP + i] = o;
}

// ---------------- mma / ldmatrix / TMA / mbarrier helpers ----------------------
__device__ __forceinline__ void mma_f16(float* d, const unsigned* a, const unsigned* b) {
    asm volatile(
        "mma.sync.aligned.m16n8k16.row.col.f32.f16.f16.f32 "
        "{%0,%1,%2,%3}, {%4,%5,%6,%7}, {%8,%9}, {%0,%1,%2,%3};\n"
        : "+f"(d[0]), "+f"(d[1]), "+f"(d[2]), "+f"(d[3])
        : "r"(a[0]), "r"(a[1]), "r"(a[2]), "r"(a[3]), "r"(b[0]), "r"(b[1]));
}
__device__ __forceinline__ void mma_f16_k8(float* d, const unsigned* a, unsigned b) {
    asm volatile(
        "mma.sync.aligned.m16n8k8.row.col.f32.f16.f16.f32 "
        "{%0,%1,%2,%3}, {%4,%5}, {%6}, {%0,%1,%2,%3};\n"
        : "+f"(d[0]), "+f"(d[1]), "+f"(d[2]), "+f"(d[3])
        : "r"(a[0]), "r"(a[1]), "r"(b));
}
__device__ __forceinline__ void ldsm_x4(unsigned* r, unsigned addr) {
    asm volatile("ldmatrix.sync.aligned.m8n8.x4.shared.b16 {%0,%1,%2,%3}, [%4];"
        : "=r"(r[0]), "=r"(r[1]), "=r"(r[2]), "=r"(r[3]) : "r"(addr));
}
__device__ __forceinline__ void ldsm_x2(unsigned* r, unsigned addr) {
    asm volatile("ldmatrix.sync.aligned.m8n8.x2.shared.b16 {%0,%1}, [%2];"
        : "=r"(r[0]), "=r"(r[1]) : "r"(addr));
}
__device__ __forceinline__ void mbar_init1(unsigned mb) {
    asm volatile("mbarrier.init.shared.b64 [%0], 1;" :: "r"(mb) : "memory");
}
__device__ __forceinline__ void mbar_expect(unsigned mb, unsigned bytes) {
    asm volatile("mbarrier.arrive.expect_tx.shared.b64 _, [%0], %1;" :: "r"(mb), "r"(bytes) : "memory");
}
__device__ __forceinline__ void mbar_wait(unsigned mb, int parity) {
    asm volatile(
        "{\n\t.reg .pred P1;\n\t"
        "W_%=:\n\t"
        "mbarrier.try_wait.parity.acquire.cta.shared::cta.b64 P1, [%0], %1, 0x989680;\n\t"
        "@P1 bra.uni D_%=;\n\t"
        "bra.uni W_%=;\n\t"
        "D_%=:\n\t}"
        :: "r"(mb), "r"(parity) : "memory");
}
__device__ __forceinline__ void tma2d(unsigned dst, const void* map, int x, int y, unsigned mb) {
    asm volatile(
        "cp.async.bulk.tensor.2d.shared::cta.global.tile.mbarrier::complete_tx::bytes "
        "[%0], [%1, {%2, %3}], [%4];"
        :: "r"(dst), "l"(map), "r"(x), "r"(y), "r"(mb) : "memory");
}

// =====================================================================
// Persistent fused gconv with TMA-fed A tiles.
// Per tile (64 GEMM rows = 2 nodes): 5 TMA box loads [72 elems x 64 rows]
// into 5 pitched smem planes (144B rows). K = 5 planes x (4 k16 + 1 k8).
// Double-buffered via 2 mbarriers (carved from dynamic smem, 128-aligned
// layout: [Ws][A0][A1][mbar] — ALL TMA dsts are 128B-aligned).
// =====================================================================
template<int NCOLS, int GCONV>
__global__ __launch_bounds__(512) void fused_gconv_t(
        const __grid_constant__ CUtensorMap mp0,
        const __grid_constant__ CUtensorMap mp1,
        const __grid_constant__ CUtensorMap mp2,
        const __grid_constant__ CUtensorMap mp3,
        const __grid_constant__ CUtensorMap mp4,
        const float* __restrict__ W, const float* __restrict__ bias,
        const float* __restrict__ hx, float* __restrict__ out) {
    extern __shared__ __align__(128) unsigned char smem_raw[];
    __half* Ws = (__half*)smem_raw;                      // [NCOLS][WSTR]

    int tid = threadIdx.x;
    unsigned WsA = (unsigned)__cvta_generic_to_shared(smem_raw);
    unsigned A0A = WsA + (unsigned)(NCOLS * WSTR * 2);   // mult of 128 past base
    unsigned A1A = A0A + ABUFB;
    unsigned mb0 = A1A + ABUFB;                          // 2 mbarriers at the end
    unsigned mb1 = mb0 + 8;

    // stage W once: [col][k'], k' = m*72 + f, orig row = f*5 + m
    for (int idx = tid; idx < KDIMP * NCOLS; idx += 512) {
        int k = idx / NCOLS, c = idx - k * NCOLS;
        int m = k / FFP, f = k - m * FFP;
        float v = (f < FF) ? W[(f * MM + m) * NCOLS + c] : 0.f;
        Ws[c * WSTR + k] = __float2half_rn(v);
    }
    if (tid == 0) {
        mbar_init1(mb0);
        mbar_init1(mb1);
        asm volatile("fence.proxy.async.shared::cta;" ::: "memory");
    }
    __syncthreads();

    const void* maps[5] = {&mp0, &mp1, &mp2, &mp3, &mp4};

    // prologue: prefetch first tile into buffer 0
    int t0 = blockIdx.x;
    if (tid == 0) {
        mbar_expect(mb0, ABUFB);
        #pragma unroll
        for (int m = 0; m < 5; m++)
            tma2d(A0A + m * PLANEB, maps[m], 0, t0 * MROWS, mb0);
    }

    int lane = tid & 31, w = tid >> 5;
    int warpM = w & 3, warpN = w >> 2;        // 4 x 4 warps: 16 rows x NCOLS/4 cols
    int g = lane >> 2, tq = lane & 3;
    constexpr int NJ = NCOLS / 32;            // n-tiles of 8 per warp (4 or 2)

    int lt = lane >> 3, lr = lane & 7;
    // A fragment offsets (within a plane)
    unsigned aOff16 = (unsigned)((warpM * 16 + (lt & 1) * 8 + lr) * 144 + (lt >> 1) * 16);
    unsigned aOff8  = (unsigned)((warpM * 16 + ((lane >> 3) & 1) * 8 + lr) * 144 + 128);
    // B fragment offsets (k16 pairs): bytes = c*752 + (lt&1)*16; add m*144 + km*32
    unsigned bOff16[NJ/2];
    #pragma unroll
    for (int p = 0; p < NJ/2; p++) {
        int c = warpN * (NCOLS/4) + p * 16 + (lt >> 1) * 8 + lr;
        bOff16[p] = WsA + (unsigned)(c * (WSTR*2) + (lt & 1) * 16);
    }
    // B fragment offset (k8): bytes = c*752 + 128; add m*144
    unsigned bOff8;
    if constexpr (NJ == 4) {
        int c = warpN * 32 + (lane >> 3) * 8 + lr;
        bOff8 = WsA + (unsigned)(c * (WSTR*2) + 128);
    } else {
        int c = warpN * 16 + ((lane >> 3) & 1) * 8 + lr;
        bOff8 = WsA + (unsigned)(c * (WSTR*2) + 128);
    }

    int ph[2] = {0, 0};
    int it = 0;
    for (int t = t0; t < NTILES; t += PGRID, ++it) {
        int bufI = it & 1;
        unsigned curA = bufI ? A1A : A0A;
        unsigned mbc  = bufI ? mb1 : mb0;

        // prefetch next tile into the other buffer (safe: all reads of that
        // buffer finished before last iteration's trailing __syncthreads)
        int tn = t + PGRID;
        if (tn < NTILES && tid == 0) {
            unsigned nxtA = bufI ? A0A : A1A;
            unsigned mbn  = bufI ? mb0 : mb1;
            mbar_expect(mbn, ABUFB);
            #pragma unroll
            for (int m = 0; m < 5; m++)
                tma2d(nxtA + m * PLANEB, maps[m], 0, tn * MROWS, mbn);
        }

        // wait current buffer
        mbar_wait(mbc, ph[bufI]);
        ph[bufI] ^= 1;

        // ---- MMA on cur ----
        float acc[NJ][4];
        #pragma unroll
        for (int j = 0; j < NJ; j++)
            #pragma unroll
            for (int q = 0; q < 4; q++) acc[j][q] = 0.f;

        #pragma unroll
        for (int m = 0; m < 5; m++) {
            unsigned aPl = curA + m * PLANEB;
            unsigned wPl = m * 144u;
            #pragma unroll
            for (int km = 0; km < 4; km++) {
                unsigned a[4];
                ldsm_x4(a, aPl + aOff16 + km * 32);
                #pragma unroll
                for (int p = 0; p < NJ/2; p++) {
                    unsigned b4[4];
                    ldsm_x4(b4, bOff16[p] + wPl + km * 32);
                    mma_f16(acc[2*p],     a, b4);
                    mma_f16(acc[2*p + 1], a, b4 + 2);
                }
            }
            // k8 tail of this plane (k' = m*72+64 .. +72)
            unsigned a2[2];
            ldsm_x2(a2, aPl + aOff8);
            if constexpr (NJ == 4) {
                unsigned b4[4];
                ldsm_x4(b4, bOff8 + wPl);
                #pragma unroll
                for (int j = 0; j < 4; j++) mma_f16_k8(acc[j], a2, b4[j]);
            } else {
                unsigned b2[2];
                ldsm_x2(b2, bOff8 + wPl);
                mma_f16_k8(acc[0], a2, b2[0]);
                mma_f16_k8(acc[1], a2, b2[1]);
            }
        }

        // ---- epilogue for tile t ----
        #pragma unroll
        for (int j = 0; j < NJ; j++) {
            int col0 = warpN * (NCOLS/4) + j * 8 + 2 * tq;
            #pragma unroll
            for (int half = 0; half < 2; half++) {
                int row = t * MROWS + warpM * 16 + g + half * 8;
                int n = row >> 5, bb = row & 31;
                #pragma unroll
                for (int q = 0; q < 2; q++) {
                    int col = col0 + q;
                    float v = acc[j][half * 2 + q] + bias[col];
                    if (GCONV == 1) {
                        v = 1.f / (1.f + __expf(-v));
                        if (col < UNITS) {
                            float h = hx[(size_t)bb * (NN*UNITS) + n*UNITS + col];
                            g_X0h[(size_t)n * NBFP + bb*FFP + 2 + col] = __float2half_rn(v * h);
                        } else {
                            g_U[(size_t)row * UNITS + (col - UNITS)] = v;
                        }
                    } else {
                        float c = tanhf(v);
                        float u = g_U[(size_t)row * UNITS + col];
                        float h = hx[(size_t)bb * (NN*UNITS) + n*UNITS + col];
                        out[(size_t)bb * (NN*UNITS) + n*UNITS + col] = u * h + (1.f - u) * c;
                    }
                }
            }
        }
        __syncthreads();   // protect cur buffer before next iteration's TMA overwrite
    }
}

// ---------------- host: tensor-map construction --------------------------------
typedef CUresult (*TMEncodeFn)(CUtensorMap*, CUtensorMapDataType, cuuint32_t, void*,
    const cuuint64_t*, const cuuint64_t*, const cuuint32_t*, const cuuint32_t*,
    CUtensorMapInterleave, CUtensorMapSwizzle, CUtensorMapL2promotion,
    CUtensorMapFloatOOBfill);

static void make_map(CUtensorMap* m, TMEncodeFn enc, void* gaddr) {
    cuuint64_t dims[2]    = {FFP, (cuuint64_t)NN * BB};   // 72 elems x 256000 rows
    cuuint64_t strides[1] = {FFP * 2};                    // 144 B row stride
    cuuint32_t box[2]     = {FFP, MROWS};                 // 72 x 64
    cuuint32_t es[2]      = {1, 1};
    enc(m, CU_TENSOR_MAP_DATA_TYPE_UINT16, 2, gaddr, dims, strides, box, es,
        CU_TENSOR_MAP_INTERLEAVE_NONE, CU_TENSOR_MAP_SWIZZLE_NONE,
        CU_TENSOR_MAP_L2_PROMOTION_L2_128B, CU_TENSOR_MAP_FLOAT_OOB_FILL_NONE);
}

// ---------------- launch --------------------------------------------------------
extern "C" void kernel_launch(void* const* d_in, const int* in_sizes, int n_in,
                              void* d_out, int out_size) {
    const float* inputs = (const float*)d_in[0];
    const float* hx     = (const float*)d_in[1];
    const float* W_ru   = (const float*)d_in[2];
    const float* b_ru   = (const float*)d_in[3];
    const float* W_c    = (const float*)d_in[4];
    const float* b_c    = (const float*)d_in[5];
    const int*   s0r    = (const int*)d_in[6];
    const int*   s0c    = (const int*)d_in[7];
    const float* s0v    = (const float*)d_in[8];
    const int*   s1r    = (const int*)d_in[9];
    const int*   s1c    = (const int*)d_in[10];
    const float* s1v    = (const float*)d_in[11];
    int E = in_sizes[6];
    float* out = (float*)d_out;

    // tensor maps for the 5 A planes (driver entry point; no -lcuda needed)
    void* fnp = nullptr;
#if CUDART_VERSION >= 12050
    cudaDriverEntryPointQueryResult qr;
    cudaGetDriverEntryPointByVersion("cuTensorMapEncodeTiled", &fnp, 12000,
                                     cudaEnableDefault, &qr);
#else
    cudaGetDriverEntryPoint("cuTensorMapEncodeTiled", &fnp, cudaEnableDefault);
#endif
    TMEncodeFn enc = (TMEncodeFn)fnp;
    void *p0, *p1, *p2, *p3, *p4;
    cudaGetSymbolAddress(&p0, g_X0h);
    cudaGetSymbolAddress(&p1, g_X1ah);
    cudaGetSymbolAddress(&p2, g_X2ah);
    cudaGetSymbolAddress(&p3, g_X1bh);
    cudaGetSymbolAddress(&p4, g_X2bh);
    CUtensorMap tm[5];
    make_map(&tm[0], enc, p0);
    make_map(&tm[1], enc, p1);
    make_map(&tm[2], enc, p2);
    make_map(&tm[3], enc, p3);
    make_map(&tm[4], enc, p4);

    // smem: [Ws][A0][A1][2 mbarriers]
    const int smem1 = 128 * WSTR * 2 + 2 * ABUFB + 128;   // 188544 B
    const int smem2 = 64  * WSTR * 2 + 2 * ABUFB + 128;   // 140416 B
    cudaFuncSetAttribute(fused_gconv_t<128,1>, cudaFuncAttributeMaxDynamicSharedMemorySize, smem1);
    cudaFuncSetAttribute(fused_gconv_t<64,2>,  cudaFuncAttributeMaxDynamicSharedMemorySize, smem2);

    // 0-2: CSR build + x0
    csr_count<<<(E + 255)/256, 256>>>(s0r, s1r, E);
    csr_scan<<<2, 1024>>>();
    long long tasks = 2LL*E + (long long)NN*NBFP;
    scatter_build<<<(unsigned)((tasks + 255)/256), 256>>>(s0r, s0c, s0v, s1r, s1c, s1v, E,
                                                          inputs, hx);

    dim3 spmmGrid(NN, 2);

    // gconv #1 (gates)
    spmm_h <<<spmmGrid, VECP>>>();
    spmm2_h<<<spmmGrid, VECP>>>();
    fused_gconv_t<128,1><<<PGRID, 512, smem1>>>(tm[0], tm[1], tm[2], tm[3], tm[4],
                                                W_ru, b_ru, hx, out);

    // gconv #2 (candidate) + final combine
    spmm_h <<<spmmGrid, VECP>>>();
    spmm2_h<<<spmmGrid, VECP>>>();
    fused_gconv_t<64,2><<<PGRID, 512, smem2>>>(tm[0], tm[1], tm[2], tm[3], tm[4],
                                               W_c, b_c, hx, out);
}